// round 14
// baseline (speedup 1.0000x reference)
#include <cuda_runtime.h>
#include <cuda_bf16.h>
#include <cuda_fp16.h>
#include <cstdint>

// ---------------------------------------------------------------------------
// Problem constants
// ---------------------------------------------------------------------------
#define BATCH   2
#define SEQ     2048
#define DMODEL  1024
#define NHEAD   16
#define DK      64
#define BH      (BATCH * NHEAD)              // 32
#define TOKENS  (BATCH * SEQ)                // 4096
#define OUT0    (TOKENS * DMODEL)            // 4,194,304
#define ATTN_N  ((long)BH * SEQ * SEQ)       // 134,217,728
#define OUT_TOTAL (OUT0 + ATTN_N)

// ---------------------------------------------------------------------------
// Scratch (static device arrays; no cudaMalloc anywhere)
// ---------------------------------------------------------------------------
__device__ __nv_bfloat16 g_Qh[TOKENS * DMODEL], g_Ql[TOKENS * DMODEL];
__device__ __nv_bfloat16 g_Kh[TOKENS * DMODEL], g_Kl[TOKENS * DMODEL];
__device__ __nv_bfloat16 g_Vh[TOKENS * DMODEL], g_Vl[TOKENS * DMODEL];
__device__ __nv_bfloat16 g_Wqh[DMODEL * DMODEL], g_Wql[DMODEL * DMODEL];
__device__ __nv_bfloat16 g_Wkh[DMODEL * DMODEL], g_Wkl[DMODEL * DMODEL];
__device__ __nv_bfloat16 g_Wvh[DMODEL * DMODEL], g_Wvl[DMODEL * DMODEL];
__device__ __nv_bfloat16 g_Woh[DMODEL * DMODEL], g_Wol[DMODEL * DMODEL];
__device__ __half g_qh[TOKENS * DMODEL], g_ql[TOKENS * DMODEL];     // fp16
__device__ __half g_kh[TOKENS * DMODEL];                             // fp16 (hi only)
__device__ __half g_vth[BH * DK * SEQ], g_vtl[BH * DK * SEQ];        // fp16 V^T hi/lo
__device__ __nv_bfloat16 g_ch[TOKENS * DMODEL], g_cl[TOKENS * DMODEL];  // ctx bf16
__device__ float g_attn[ATTN_N];                 // fallback if d_out lacks attn

// ---------------------------------------------------------------------------
// Helpers
// ---------------------------------------------------------------------------
__device__ __forceinline__ uint32_t smem_u32(const void* p) {
    uint32_t a;
    asm("{ .reg .u64 t; cvta.to.shared.u64 t, %1; cvt.u32.u64 %0, t; }"
        : "=r"(a) : "l"(p));
    return a;
}
#define SWZ(off) ((off) ^ (((off) >> 3) & 0x70))

__device__ __forceinline__ void ldsm_x4(uint32_t& r0, uint32_t& r1,
                                        uint32_t& r2, uint32_t& r3, uint32_t a) {
    asm volatile("ldmatrix.sync.aligned.m8n8.x4.shared.b16 {%0,%1,%2,%3}, [%4];"
                 : "=r"(r0), "=r"(r1), "=r"(r2), "=r"(r3) : "r"(a));
}
__device__ __forceinline__ void mma_bf16(float* c, const uint32_t* a,
                                         uint32_t b0, uint32_t b1) {
    asm volatile(
        "mma.sync.aligned.m16n8k16.row.col.f32.bf16.bf16.f32 "
        "{%0,%1,%2,%3}, {%4,%5,%6,%7}, {%8,%9}, {%0,%1,%2,%3};"
        : "+f"(c[0]), "+f"(c[1]), "+f"(c[2]), "+f"(c[3])
        : "r"(a[0]), "r"(a[1]), "r"(a[2]), "r"(a[3]), "r"(b0), "r"(b1));
}
__device__ __forceinline__ void mma_f16(float* c, const uint32_t* a,
                                        uint32_t b0, uint32_t b1) {
    asm volatile(
        "mma.sync.aligned.m16n8k16.row.col.f32.f16.f16.f32 "
        "{%0,%1,%2,%3}, {%4,%5,%6,%7}, {%8,%9}, {%0,%1,%2,%3};"
        : "+f"(c[0]), "+f"(c[1]), "+f"(c[2]), "+f"(c[3])
        : "r"(a[0]), "r"(a[1]), "r"(a[2]), "r"(a[3]), "r"(b0), "r"(b1));
}
__device__ __forceinline__ void cp16(uint32_t dst, const void* src) {
    asm volatile("cp.async.cg.shared.global [%0], [%1], 16;"
                 :: "r"(dst), "l"(src) : "memory");
}
#define CP_COMMIT() asm volatile("cp.async.commit_group;" ::: "memory")
#define CP_WAIT1()  asm volatile("cp.async.wait_group 1;" ::: "memory")
#define CP_WAIT0()  asm volatile("cp.async.wait_group 0;" ::: "memory")

__device__ __forceinline__ uint32_t pack_half(float lo, float hi) {
    uint32_t r;
    asm("cvt.rn.f16x2.f32 %0, %1, %2;" : "=r"(r) : "f"(hi), "f"(lo));
    return r;
}

// ---------------------------------------------------------------------------
// One-launch fp32 -> bf16 hi/lo split over all 7 inputs (grid.y = segment)
// ---------------------------------------------------------------------------
struct SplitArgs {
    const float* x[7];
    __nv_bfloat16* h[7];
    __nv_bfloat16* l[7];
    int n4[7];
};

__global__ void __launch_bounds__(256)
split_all(SplitArgs a)
{
    const int seg = blockIdx.y;
    const int i = blockIdx.x * 256 + threadIdx.x;
    if (i >= a.n4[seg]) return;
    float4 v = ((const float4*)a.x[seg])[i];
    __nv_bfloat16 h0 = __float2bfloat16(v.x), h1 = __float2bfloat16(v.y);
    __nv_bfloat16 h2 = __float2bfloat16(v.z), h3 = __float2bfloat16(v.w);
    float l0 = v.x - __bfloat162float(h0), l1 = v.y - __bfloat162float(h1);
    float l2 = v.z - __bfloat162float(h2), l3 = v.w - __bfloat162float(h3);
    uint2 hv, lv;
    hv.x = (uint32_t)__bfloat16_as_ushort(h0) | ((uint32_t)__bfloat16_as_ushort(h1) << 16);
    hv.y = (uint32_t)__bfloat16_as_ushort(h2) | ((uint32_t)__bfloat16_as_ushort(h3) << 16);
    lv.x = (uint32_t)__bfloat16_as_ushort(__float2bfloat16(l0)) |
           ((uint32_t)__bfloat16_as_ushort(__float2bfloat16(l1)) << 16);
    lv.y = (uint32_t)__bfloat16_as_ushort(__float2bfloat16(l2)) |
           ((uint32_t)__bfloat16_as_ushort(__float2bfloat16(l3)) << 16);
    ((uint2*)a.h[seg])[i] = hv;
    ((uint2*)a.l[seg])[i] = lv;
}

// ---------------------------------------------------------------------------
// mma.sync split-bf16 GEMM, 3-pass, KT=32 PACKED-ROW layout:
// each smem row = 128B = [32 k of HI | 32 k of LO], SW128 swizzle.
// Stage = A 16K + B 8K = 24K; 2 stages = 48K.  __launch_bounds__(256,4)
// caps regs at 64 so 4 CTAs/SM fit (2x occupancy vs R12).
// Tile M=128, N=64; 256 threads (8 warps, 4x2 grid, 32x32/warp).
// EPI 0: bias + fp16 hi/lo split store, ld 1024          [Q projection]
// EPI 1: bias + fp16 hi/lo split, transposed per-head    [V projection]
// EPI 2: bias + fp16 hi-only store, ld 1024              [K projection]
// EPI 4: bias + fp32 store, ld 1024                      [output projection]
// ---------------------------------------------------------------------------
#define MT 128
#define NT 64
#define KT 32
#define OFF_B 16384
#define STG_STRIDE 24576
#define SM_PIPE  49152

template <int EPI>
__global__ void __launch_bounds__(256, 4)
mma_gemm(const __nv_bfloat16* __restrict__ Ah, const __nv_bfloat16* __restrict__ Al,
         const __nv_bfloat16* __restrict__ Bh, const __nv_bfloat16* __restrict__ Bl,
         const float* __restrict__ bias, float* __restrict__ outF,
         __half* __restrict__ outH, __half* __restrict__ outL,
         int K, int lda, int ldb)
{
    extern __shared__ uint8_t dsm[];
    const uint32_t sb = smem_u32(dsm);
    const int tid = threadIdx.x, wid = tid >> 5, lane = tid & 31;
    const int wm = wid >> 1, wn = wid & 1;
    const int n0 = blockIdx.x * NT, m0 = blockIdx.y * MT;

    float acc[2][4][4];
#pragma unroll
    for (int i = 0; i < 2; i++)
#pragma unroll
        for (int j = 0; j < 4; j++)
#pragma unroll
            for (int r = 0; r < 4; r++) acc[i][j][r] = 0.0f;

    const int lrow = lane & 15, lkh = lane >> 4;

    const int ntiles = K / KT;
    // Packed-row stage: chunk c16 in [0,8): c16<4 -> hi plane k-bytes, else lo.
    auto stage = [&](int kti, int buf) {
        const uint32_t b0 = sb + buf * STG_STRIDE;
        const int kt = kti * KT;
#pragma unroll
        for (int i = 0; i < 4; i++) {                 // A: 1024 chunks
            int chunk = tid + i * 256;
            int row = chunk >> 3, c16 = chunk & 7;
            const __nv_bfloat16* src = (c16 < 4)
                ? Ah + (long)(m0 + row) * lda + kt + c16 * 8
                : Al + (long)(m0 + row) * lda + kt + (c16 - 4) * 8;
            cp16(b0 + SWZ((uint32_t)(row * 128 + c16 * 16)), src);
        }
#pragma unroll
        for (int i = 0; i < 2; i++) {                 // B: 512 chunks
            int chunk = tid + i * 256;
            int row = chunk >> 3, c16 = chunk & 7;
            const __nv_bfloat16* src = (c16 < 4)
                ? Bh + (long)(n0 + row) * ldb + kt + c16 * 8
                : Bl + (long)(n0 + row) * ldb + kt + (c16 - 4) * 8;
            cp16(b0 + OFF_B + SWZ((uint32_t)(row * 128 + c16 * 16)), src);
        }
    };
    stage(0, 0);
    CP_COMMIT();
    for (int t = 0; t < ntiles; t++) {
        if (t + 1 < ntiles) { stage(t + 1, (t + 1) & 1); CP_COMMIT(); CP_WAIT1(); }
        else { CP_WAIT0(); }
        __syncthreads();
        const uint32_t b0 = sb + (t & 1) * STG_STRIDE;
#pragma unroll
        for (int ks = 0; ks < 2; ks++) {
            const uint32_t kbh = ks * 32 + lkh * 16;        // hi half of row
            const uint32_t kbl = 64 + ks * 32 + lkh * 16;   // lo half of row
            uint32_t ah[2][4], al[2][4];
#pragma unroll
            for (int ms = 0; ms < 2; ms++) {
                uint32_t rbase = (uint32_t)(wm * 32 + ms * 16 + lrow) * 128;
                ldsm_x4(ah[ms][0], ah[ms][1], ah[ms][2], ah[ms][3],
                        b0 + SWZ(rbase + kbh));
                ldsm_x4(al[ms][0], al[ms][1], al[ms][2], al[ms][3],
                        b0 + SWZ(rbase + kbl));
            }
            uint32_t bh[4][2], bl[4][2];
#pragma unroll
            for (int half = 0; half < 2; half++) {
                uint32_t rbase = (uint32_t)(wn * 32 + half * 16 + lrow) * 128;
                uint32_t r0, r1, r2, r3;
                ldsm_x4(r0, r1, r2, r3, b0 + OFF_B + SWZ(rbase + kbh));
                bh[half * 2 + 0][0] = r0; bh[half * 2 + 0][1] = r2;
                bh[half * 2 + 1][0] = r1; bh[half * 2 + 1][1] = r3;
                ldsm_x4(r0, r1, r2, r3, b0 + OFF_B + SWZ(rbase + kbl));
                bl[half * 2 + 0][0] = r0; bl[half * 2 + 0][1] = r2;
                bl[half * 2 + 1][0] = r1; bl[half * 2 + 1][1] = r3;
            }
#pragma unroll
            for (int ms = 0; ms < 2; ms++)
#pragma unroll
                for (int nb = 0; nb < 4; nb++) {
                    mma_bf16(acc[ms][nb], ah[ms], bh[nb][0], bh[nb][1]);
                    mma_bf16(acc[ms][nb], al[ms], bh[nb][0], bh[nb][1]);
                    mma_bf16(acc[ms][nb], ah[ms], bl[nb][0], bl[nb][1]);
                }
        }
        __syncthreads();
    }

    // ---- epilogue: regs -> padded smem staging -> coalesced global ----
    float* st = (float*)dsm;                     // [128][65] fp32 (33280 B)
    {
        const int lr = lane >> 2, lc = (lane & 3) * 2;
#pragma unroll
        for (int ms = 0; ms < 2; ms++)
#pragma unroll
            for (int nb = 0; nb < 4; nb++) {
                int r = wm * 32 + ms * 16 + lr;
                int c = wn * 32 + nb * 8 + lc;
                st[r * 65 + c]            = acc[ms][nb][0];
                st[r * 65 + c + 1]        = acc[ms][nb][1];
                st[(r + 8) * 65 + c]      = acc[ms][nb][2];
                st[(r + 8) * 65 + c + 1]  = acc[ms][nb][3];
            }
    }
    __syncthreads();

    if (EPI == 4) {            // OUT: fp32 + bias
        for (int i = tid; i < MT * NT; i += 256) {
            int row = i >> 6, c = i & 63;
            outF[(long)(m0 + row) * 1024 + n0 + c] = st[row * 65 + c] + bias[n0 + c];
        }
    } else if (EPI == 0) {     // Q: bias + fp16 hi/lo split
        for (int i = tid; i < MT * NT; i += 256) {
            int row = i >> 6, c = i & 63;
            float v = st[row * 65 + c] + bias[n0 + c];
            long o = (long)(m0 + row) * 1024 + n0 + c;
            __half h = __float2half_rn(v);
            outH[o] = h;
            outL[o] = __float2half_rn(v - __half2float(h));
        }
    } else if (EPI == 2) {     // K: bias + fp16 hi only
        for (int i = tid; i < MT * NT; i += 256) {
            int row = i >> 6, c = i & 63;
            float v = st[row * 65 + c] + bias[n0 + c];
            outH[(long)(m0 + row) * 1024 + n0 + c] = __float2half_rn(v);
        }
    } else {                   // V: bias + fp16 hi/lo, transposed [BH,64,S]
        for (int i = tid; i < MT * NT; i += 256) {
            int j = i >> 7, rl = i & 127;
            int r = m0 + rl, cg = n0 + j;
            float v = st[rl * 65 + j] + bias[cg];
            int b = r >> 11, s = r & 2047, hh = cg >> 6, jj = cg & 63;
            long o = ((long)(b * 16 + hh) * 64 + jj) * 2048 + s;
            __half h = __float2half_rn(v);
            outH[o] = h;
            outL[o] = __float2half_rn(v - __half2float(h));
        }
    }
    (void)outL;
}

// ---------------------------------------------------------------------------
// Fused scores + softmax + context — fp16 (unchanged from R12).
// Pass A: S via qh*kh 1-pass -> row sums of exp.
// Pass B: S 2-pass (qh*kh + ql*kh), normalize, store attn once,
//         P -> fp16 plane, O += P @ (Vh + Vl), cross-wn reduce, bf16 ctx.
// ---------------------------------------------------------------------------
#define FB_QH   0
#define FB_QL   16384
#define FB_ST0  32768
#define FB_STRIDE 32768
#define FB_PART 98304           // float[2][128]
#define FB_ROWL 99328           // float[128]
#define FB_SM   99840

__global__ void __launch_bounds__(256)
fused_attn_k(const __half* __restrict__ qh, const __half* __restrict__ ql,
             const __half* __restrict__ kh,
             const __half* __restrict__ vth, const __half* __restrict__ vtl,
             float* __restrict__ attn,
             __nv_bfloat16* __restrict__ ch, __nv_bfloat16* __restrict__ cl)
{
    extern __shared__ uint8_t dsm[];
    const uint32_t sb = smem_u32(dsm);
    const int tid = threadIdx.x, wid = tid >> 5, lane = tid & 31;
    const int wm = wid >> 1, wn = wid & 1;
    const int lrow = lane & 15, lkh = lane >> 4;
    const int lr = lane >> 2, lc = lane & 3;
    const int m0 = blockIdx.x * 128;
    const int z = blockIdx.y;
    const long base = (long)(z >> 4) * 2048L * 1024 + (long)(z & 15) * 64;
    const __half* qh_h = qh + base;
    const __half* ql_h = ql + base;
    const __half* kh_h = kh + base;
    const __half* vh_h = vth + (long)z * 64L * 2048;
    const __half* vl_h = vtl + (long)z * 64L * 2048;

    float* part  = (float*)(dsm + FB_PART);
    float* row_l = (float*)(dsm + FB_ROWL);

    auto stage_k_hi = [&](int t, int buf) {
        const uint32_t sd = sb + FB_ST0 + buf * FB_STRIDE;
#pragma unroll
        for (int i = 0; i < 2; i++) {
            int chunk = tid + i * 256;
            int row = chunk >> 3, c16 = chunk & 7;
            long g = (long)(t * 64 + row) * 1024 + c16 * 8;
            uint32_t so = SWZ((uint32_t)(row * 128 + c16 * 16));
            cp16(sd + so, kh_h + g);
        }
    };
    auto stage_kv = [&](int t, int buf) {
        const uint32_t sd = sb + FB_ST0 + buf * FB_STRIDE;
#pragma unroll
        for (int i = 0; i < 2; i++) {
            int chunk = tid + i * 256;
            int row = chunk >> 3, c16 = chunk & 7;
            long g = (long)(t * 64 + row) * 1024 + c16 * 8;
            uint32_t so = SWZ((uint32_t)(row * 128 + c16 * 16));
            cp16(sd + so, kh_h + g);
        }
#pragma unroll
        for (int i = 0; i < 2; i++) {
            int chunk = tid + i * 256;               // row = dk 0..63
            int row = chunk >> 3, c16 = chunk & 7;
            long g = (long)row * 2048 + t * 64 + c16 * 8;
            uint32_t so = SWZ((uint32_t)(row * 128 + c16 * 16));
            cp16(sd + 8192 + so, vh_h + g);
            cp16(sd + 16384 + so, vl_h + g);
        }
    };

    auto compute_tile_hi = [&](int buf, float acc[2][4][4]) {
#pragma unroll
        for (int i = 0; i < 2; i++)
#pragma unroll
            for (int j = 0; j < 4; j++)
#pragma unroll
                for (int r = 0; r < 4; r++) acc[i][j][r] = 0.0f;
        const uint32_t kbh = sb + FB_ST0 + buf * FB_STRIDE;
#pragma unroll
        for (int ks = 0; ks < 4; ks++) {
            const uint32_t kb = ks * 32 + lkh * 16;
            uint32_t ah[2][4];
#pragma unroll
            for (int ms = 0; ms < 2; ms++) {
                uint32_t ro = (uint32_t)(wm * 32 + ms * 16 + lrow) * 128 + kb;
                ldsm_x4(ah[ms][0], ah[ms][1], ah[ms][2], ah[ms][3], sb + FB_QH + SWZ(ro));
            }
            uint32_t bh[4][2];
#pragma unroll
            for (int half = 0; half < 2; half++) {
                uint32_t ro = (uint32_t)(wn * 32 + half * 16 + lrow) * 128 + kb;
                uint32_t r0, r1, r2, r3;
                ldsm_x4(r0, r1, r2, r3, kbh + SWZ(ro));
                bh[half * 2 + 0][0] = r0; bh[half * 2 + 0][1] = r2;
                bh[half * 2 + 1][0] = r1; bh[half * 2 + 1][1] = r3;
            }
#pragma unroll
            for (int ms = 0; ms < 2; ms++)
#pragma unroll
                for (int nb = 0; nb < 4; nb++)
                    mma_f16(acc[ms][nb], ah[ms], bh[nb][0], bh[nb][1]);
        }
    };
    auto compute_tile = [&](int buf, float acc[2][4][4]) {
#pragma unroll
        for (int i = 0; i < 2; i++)
#pragma unroll
            for (int j = 0; j < 4; j++)
#pragma unroll
                for (int r = 0; r < 4; r++) acc[i][j][r] = 0.0f;
        const uint32_t kbh = sb + FB_ST0 + buf * FB_STRIDE;
#pragma unroll
        for (int ks = 0; ks < 4; ks++) {
            const uint32_t kb = ks * 32 + lkh * 16;
            uint32_t ah[2][4], al[2][4];
#pragma unroll
            for (int ms = 0; ms < 2; ms++) {
                uint32_t ro = (uint32_t)(wm * 32 + ms * 16 + lrow) * 128 + kb;
                ldsm_x4(ah[ms][0], ah[ms][1], ah[ms][2], ah[ms][3], sb + FB_QH + SWZ(ro));
                ldsm_x4(al[ms][0], al[ms][1], al[ms][2], al[ms][3], sb + FB_QL + SWZ(ro));
            }
            uint32_t bh[4][2];
#pragma unroll
            for (int half = 0; half < 2; half++) {
                uint32_t ro = (uint32_t)(wn * 32 + half * 16 + lrow) * 128 + kb;
                uint32_t r0, r1, r2, r3;
                ldsm_x4(r0, r1, r2, r3, kbh + SWZ(ro));
                bh[half * 2 + 0][0] = r0; bh[half * 2 + 0][1] = r2;
                bh[half * 2 + 1][0] = r1; bh[half * 2 + 1][1] = r3;
            }
#pragma unroll
            for (int ms = 0; ms < 2; ms++)
#pragma unroll
                for (int nb = 0; nb < 4; nb++) {
                    mma_f16(acc[ms][nb], ah[ms], bh[nb][0], bh[nb][1]);
                    mma_f16(acc[ms][nb], al[ms], bh[nb][0], bh[nb][1]);
                }
        }
    };

    // ---- prologue: q tile + k tile 0 ----
#pragma unroll
    for (int i = 0; i < 4; i++) {
        int chunk = tid + i * 256;
        int row = chunk >> 3, c16 = chunk & 7;
        long g = (long)(m0 + row) * 1024 + c16 * 8;
        uint32_t so = SWZ((uint32_t)(row * 128 + c16 * 16));
        cp16(sb + FB_QH + so, qh_h + g);
        cp16(sb + FB_QL + so, ql_h + g);
    }
    if (tid < 128) row_l[tid] = 0.0f;
    stage_k_hi(0, 0);
    CP_COMMIT();

    float acc[2][4][4];

    // ---- pass A: approximate S (fp16 hi*hi), row sums of exp ----
    for (int t = 0; t < 32; t++) {
        if (t + 1 < 32) { stage_k_hi(t + 1, (t + 1) & 1); CP_COMMIT(); CP_WAIT1(); }
        else { CP_WAIT0(); }
        __syncthreads();
        compute_tile_hi(t & 1, acc);
#pragma unroll
        for (int ms = 0; ms < 2; ms++) {
            float s0 = 0.0f, s1 = 0.0f;
#pragma unroll
            for (int nb = 0; nb < 4; nb++) {
                s0 += __expf(acc[ms][nb][0] * 0.125f) + __expf(acc[ms][nb][1] * 0.125f);
                s1 += __expf(acc[ms][nb][2] * 0.125f) + __expf(acc[ms][nb][3] * 0.125f);
            }
            s0 += __shfl_xor_sync(0xffffffffu, s0, 1);
            s0 += __shfl_xor_sync(0xffffffffu, s0, 2);
            s1 += __shfl_xor_sync(0xffffffffu, s1, 1);
            s1 += __shfl_xor_sync(0xffffffffu, s1, 2);
            if (lc == 0) {
                part[wn * 128 + wm * 32 + ms * 16 + lr]     = s0;
                part[wn * 128 + wm * 32 + ms * 16 + 8 + lr] = s1;
            }
        }
        __syncthreads();
        if (tid < 128) row_l[tid] += part[tid] + part[128 + tid];
    }
    __syncthreads();
    float inv[2][2];
#pragma unroll
    for (int ms = 0; ms < 2; ms++) {
        inv[ms][0] = 1.0f / row_l[wm * 32 + ms * 16 + lr];
        inv[ms][1] = 1.0f / row_l[wm * 32 + ms * 16 + 8 + lr];
    }

    float accO[2][8][4];
#pragma unroll
    for (int ms = 0; ms < 2; ms++)
#pragma unroll
        for (int dn = 0; dn < 8; dn++)
#pragma unroll
            for (int r = 0; r < 4; r++) accO[ms][dn][r] = 0.0f;

    // ---- pass B: 2-pass S, normalize, store attn, O += P @ (Vh + Vl) ----
    stage_kv(0, 0);
    CP_COMMIT();
    for (int t = 0; t < 32; t++) {
        if (t + 1 < 32) { stage_kv(t + 1, (t + 1) & 1); CP_COMMIT(); CP_WAIT1(); }
        else { CP_WAIT0(); }
        __syncthreads();
        compute_tile(t & 1, acc);

#pragma unroll
        for (int ms = 0; ms < 2; ms++)
#pragma unroll
            for (int nb = 0; nb < 4; nb++) {
                acc[ms][nb][0] = __expf(acc[ms][nb][0] * 0.125f) * inv[ms][0];
                acc[ms][nb][1] = __expf(acc[ms][nb][1] * 0.125f) * inv[ms][0];
                acc[ms][nb][2] = __expf(acc[ms][nb][2] * 0.125f) * inv[ms][1];
                acc[ms][nb][3] = __expf(acc[ms][nb][3] * 0.125f) * inv[ms][1];
            }

        const int colb = t * 64 + wn * 32 + lc * 2;
#pragma unroll
        for (int ms = 0; ms < 2; ms++) {
            long rb0 = ((long)z * 2048 + m0 + wm * 32 + ms * 16 + lr) * 2048;
            long rb1 = rb0 + 8L * 2048;
#pragma unroll
            for (int nb = 0; nb < 4; nb++) {
                *(float2*)(attn + rb0 + colb + nb * 8) =
                    make_float2(acc[ms][nb][0], acc[ms][nb][1]);
                *(float2*)(attn + rb1 + colb + nb * 8) =
                    make_float2(acc[ms][nb][2], acc[ms][nb][3]);
            }
        }

        // O += P @ (Vh + Vl)
        const uint32_t vbh = sb + FB_ST0 + (t & 1) * FB_STRIDE + 8192;
        const uint32_t vbl = vbh + 8192;
#pragma unroll
        for (int kh2 = 0; kh2 < 2; kh2++) {
            uint32_t vh[8][2], vl[8][2];
#pragma unroll
            for (int dh = 0; dh < 4; dh++) {
                uint32_t ro = (uint32_t)(dh * 16 + lrow) * 128 +
                              (uint32_t)(wn * 32 + kh2 * 16) * 2 + lkh * 16;
                uint32_t r0, r1, r2, r3;
                ldsm_x4(r0, r1, r2, r3, vbh + SWZ(ro));
                vh[dh * 2 + 0][0] = r0; vh[dh * 2 + 0][1] = r2;
                vh[dh * 2 + 1][0] = r1; vh[dh * 2 + 1][1] = r3;
                ldsm_x4(r0, r1, r2, r3, vbl + SWZ(ro));
                vl[dh * 2 + 0][0] = r0; vl[dh * 2 + 0][1] = r2;
                vl[dh * 2 + 1][0] = r1; vl[dh * 2 + 1][1] = r3;
            }
#pragma unroll
            for (int ms = 0; ms < 2; ms++) {
                const float* c0 = acc[ms][2 * kh2];
                const float* c1 = acc[ms][2 * kh2 + 1];
                uint32_t ph[4];
                ph[0] = pack_half(c0[0], c0[1]);
                ph[1] = pack_half(c0[2], c0[3]);
                ph[2] = pack_half(c1[0], c1[1]);
                ph[3] = pack_half(c1[2], c1[3]);
#pragma unroll
                for (int dn = 0; dn < 8; dn++) {
                    mma_f16(accO[ms][dn], ph, vh[dn][0], vh[dn][1]);
                    mma_f16(accO[ms][dn], ph, vl[dn][0], vl[dn][1]);
                }
            }
        }
        __syncthreads();
    }

    // ---- ctx epilogue: cross-wn reduce in smem, bf16 split store [B,S,D] ----
    float* st = (float*)dsm;
    {
        const int lc2 = lc * 2;
        if (wn == 0) {
#pragma unroll
            for (int ms = 0; ms < 2; ms++)
#pragma unroll
                for (int dn = 0; dn < 8; dn++) {
                    int r = wm * 32 + ms * 16 + lr;
                    int c = dn * 8 + lc2;
                    st[r * 65 + c]           = accO[ms][dn][0];
                    st[r * 65 + c + 1]       = accO[ms][dn][1];
                    st[(r + 8) * 65 + c]     = accO[ms][dn][2];
                    st[(r + 8) * 65 + c + 1] = accO[ms][dn][3];
                }
        }
        __syncthreads();
        if (wn == 1) {
#pragma unroll
            for (int ms = 0; ms < 2; ms++)
#pragma unroll
                for (int dn = 0; dn < 8; dn++) {
                    int r = wm * 32 + ms * 16 + lr;
                    int c = dn * 8 + lc2;
                    st[r * 65 + c]           += accO[ms][dn][0];
                    st[r * 65 + c + 1]       += accO[ms][dn][1];
                    st[(r + 8) * 65 + c]     += accO[ms][dn][2];
                    st[(r + 8) * 65 + c + 1] += accO[ms][dn][3];
                }
        }
        __syncthreads();
    }
    {
        const int b = z >> 4, hh = z & 15;
        for (int i = tid; i < 128 * 64; i += 256) {
            int row = i >> 6, c = i & 63;
            float v = st[row * 65 + c];
            long o = (long)((b << 11) + m0 + row) * 1024 + hh * 64 + c;
            __nv_bfloat16 h = __float2bfloat16(v);
            ch[o] = h;
            cl[o] = __float2bfloat16(v - __bfloat162float(h));
        }
    }
}

// ---------------------------------------------------------------------------
extern "C" void kernel_launch(void* const* d_in, const int* in_sizes, int n_in,
                              void* d_out, int out_size)
{
    const float* Q  = (const float*)d_in[0];
    const float* K  = (const float*)d_in[1];
    const float* V  = (const float*)d_in[2];
    const float* Wq = (const float*)d_in[3];
    const float* bq = (const float*)d_in[4];
    const float* Wk = (const float*)d_in[5];
    const float* bk = (const float*)d_in[6];
    const float* Wv = (const float*)d_in[7];
    const float* bv = (const float*)d_in[8];
    const float* Wo = (const float*)d_in[9];
    const float* bo = (const float*)d_in[10];
    float* out = (float*)d_out;

    __nv_bfloat16 *Qh, *Ql, *Kh, *Kl, *Vh, *Vl;
    __nv_bfloat16 *Wqh, *Wql, *Wkh, *Wkl, *Wvh, *Wvl, *Woh, *Wol;
    __half *qh, *ql, *kh, *vth, *vtl;
    __nv_bfloat16 *ch, *cl;
    float* attn_scratch;
    cudaGetSymbolAddress((void**)&Qh, g_Qh);   cudaGetSymbolAddress((void**)&Ql, g_Ql);
    cudaGetSymbolAddress((void**)&Kh, g_Kh);   cudaGetSymbolAddress((void**)&Kl, g_Kl);
    cudaGetSymbolAddress((void**)&Vh, g_Vh);   cudaGetSymbolAddress((void**)&Vl, g_Vl);
    cudaGetSymbolAddress((void**)&Wqh, g_Wqh); cudaGetSymbolAddress((void**)&Wql, g_Wql);
    cudaGetSymbolAddress((void**)&Wkh, g_Wkh); cudaGetSymbolAddress((void**)&Wkl, g_Wkl);
    cudaGetSymbolAddress((void**)&Wvh, g_Wvh); cudaGetSymbolAddress((void**)&Wvl, g_Wvl);
    cudaGetSymbolAddress((void**)&Woh, g_Woh); cudaGetSymbolAddress((void**)&Wol, g_Wol);
    cudaGetSymbolAddress((void**)&qh, g_qh);   cudaGetSymbolAddress((void**)&ql, g_ql);
    cudaGetSymbolAddress((void**)&kh, g_kh);
    cudaGetSymbolAddress((void**)&vth, g_vth); cudaGetSymbolAddress((void**)&vtl, g_vtl);
    cudaGetSymbolAddress((void**)&ch, g_ch);   cudaGetSymbolAddress((void**)&cl, g_cl);
    cudaGetSymbolAddress((void**)&attn_scratch, g_attn);

    float* attn = ((long)out_size >= OUT_TOTAL) ? (out + OUT0) : attn_scratch;

    cudaFuncSetAttribute(mma_gemm<0>, cudaFuncAttributeMaxDynamicSharedMemorySize, SM_PIPE);
    cudaFuncSetAttribute(mma_gemm<1>, cudaFuncAttributeMaxDynamicSharedMemorySize, SM_PIPE);
    cudaFuncSetAttribute(mma_gemm<2>, cudaFuncAttributeMaxDynamicSharedMemorySize, SM_PIPE);
    cudaFuncSetAttribute(mma_gemm<4>, cudaFuncAttributeMaxDynamicSharedMemorySize, SM_PIPE);
    cudaFuncSetAttribute(fused_attn_k, cudaFuncAttributeMaxDynamicSharedMemorySize, FB_SM);

    // 0) One-launch split of all 7 fp32 inputs into bf16 hi/lo
    {
        SplitArgs a;
        a.x[0] = Q;  a.h[0] = Qh;  a.l[0] = Ql;  a.n4[0] = TOKENS * DMODEL / 4;
        a.x[1] = K;  a.h[1] = Kh;  a.l[1] = Kl;  a.n4[1] = TOKENS * DMODEL / 4;
        a.x[2] = V;  a.h[2] = Vh;  a.l[2] = Vl;  a.n4[2] = TOKENS * DMODEL / 4;
        a.x[3] = Wq; a.h[3] = Wqh; a.l[3] = Wql; a.n4[3] = DMODEL * DMODEL / 4;
        a.x[4] = Wk; a.h[4] = Wkh; a.l[4] = Wkl; a.n4[4] = DMODEL * DMODEL / 4;
        a.x[5] = Wv; a.h[5] = Wvh; a.l[5] = Wvl; a.n4[5] = DMODEL * DMODEL / 4;
        a.x[6] = Wo; a.h[6] = Woh; a.l[6] = Wol; a.n4[6] = DMODEL * DMODEL / 4;
        dim3 gs((TOKENS * DMODEL / 4 + 255) / 256, 7, 1);
        split_all<<<gs, 256>>>(a);
    }

    // 1-3) Projections (bf16 3-pass, KT=32 packed): Q->hi/lo, K->hi, V->hi/lo^T
    dim3 gp(DMODEL / NT, TOKENS / MT, 1);                       // (16, 32)
    mma_gemm<0><<<gp, 256, SM_PIPE>>>(Qh, Ql, Wqh, Wql, bq, nullptr, qh, ql,
                                      DMODEL, DMODEL, DMODEL);
    mma_gemm<2><<<gp, 256, SM_PIPE>>>(Kh, Kl, Wkh, Wkl, bk, nullptr, kh, nullptr,
                                      DMODEL, DMODEL, DMODEL);
    mma_gemm<1><<<gp, 256, SM_PIPE>>>(Vh, Vl, Wvh, Wvl, bv, nullptr, vth, vtl,
                                      DMODEL, DMODEL, DMODEL);

    // 4) Fused scores + softmax + context (2-pass S, 2-pass O)
    dim3 gf(SEQ / 128, BH, 1);                                  // (16, 32)
    fused_attn_k<<<gf, 256, FB_SM>>>(qh, ql, kh, vth, vtl, attn, ch, cl);

    // 5) Output projection: ctx @ Wo^T + bo -> out fp32 (bf16 3-pass)
    mma_gemm<4><<<gp, 256, SM_PIPE>>>(ch, cl, Woh, Wol, bo, out, nullptr, nullptr,
                                      DMODEL, DMODEL, DMODEL);

    (void)n_in; (void)in_sizes;
}

// round 15
// speedup vs baseline: 1.1583x; 1.1583x over previous
#include <cuda_runtime.h>
#include <cuda_bf16.h>
#include <cuda_fp16.h>
#include <cstdint>

// ---------------------------------------------------------------------------
// Problem constants
// ---------------------------------------------------------------------------
#define BATCH   2
#define SEQ     2048
#define DMODEL  1024
#define NHEAD   16
#define DK      64
#define BH      (BATCH * NHEAD)              // 32
#define TOKENS  (BATCH * SEQ)                // 4096
#define OUT0    (TOKENS * DMODEL)            // 4,194,304
#define ATTN_N  ((long)BH * SEQ * SEQ)       // 134,217,728
#define OUT_TOTAL (OUT0 + ATTN_N)

// ---------------------------------------------------------------------------
// Scratch (static device arrays; no cudaMalloc anywhere)
// ---------------------------------------------------------------------------
__device__ __nv_bfloat16 g_Qh[TOKENS * DMODEL], g_Ql[TOKENS * DMODEL];
__device__ __nv_bfloat16 g_Kh[TOKENS * DMODEL], g_Kl[TOKENS * DMODEL];
__device__ __nv_bfloat16 g_Vh[TOKENS * DMODEL], g_Vl[TOKENS * DMODEL];
__device__ __nv_bfloat16 g_Wqh[DMODEL * DMODEL], g_Wql[DMODEL * DMODEL];
__device__ __nv_bfloat16 g_Wkh[DMODEL * DMODEL], g_Wkl[DMODEL * DMODEL];
__device__ __nv_bfloat16 g_Wvh[DMODEL * DMODEL], g_Wvl[DMODEL * DMODEL];
__device__ __nv_bfloat16 g_Woh[DMODEL * DMODEL], g_Wol[DMODEL * DMODEL];
__device__ __half g_qh[TOKENS * DMODEL], g_ql[TOKENS * DMODEL];     // fp16
__device__ __half g_kh[TOKENS * DMODEL];                             // fp16 (hi only)
__device__ __half g_vth[BH * DK * SEQ], g_vtl[BH * DK * SEQ];        // fp16 V^T hi/lo
__device__ __nv_bfloat16 g_ch[TOKENS * DMODEL], g_cl[TOKENS * DMODEL];  // ctx bf16
__device__ float g_attn[ATTN_N];                 // fallback if d_out lacks attn

// ---------------------------------------------------------------------------
// Helpers
// ---------------------------------------------------------------------------
__device__ __forceinline__ uint32_t smem_u32(const void* p) {
    uint32_t a;
    asm("{ .reg .u64 t; cvta.to.shared.u64 t, %1; cvt.u32.u64 %0, t; }"
        : "=r"(a) : "l"(p));
    return a;
}
#define SWZ(off) ((off) ^ (((off) >> 3) & 0x70))

__device__ __forceinline__ void ldsm_x4(uint32_t& r0, uint32_t& r1,
                                        uint32_t& r2, uint32_t& r3, uint32_t a) {
    asm volatile("ldmatrix.sync.aligned.m8n8.x4.shared.b16 {%0,%1,%2,%3}, [%4];"
                 : "=r"(r0), "=r"(r1), "=r"(r2), "=r"(r3) : "r"(a));
}
__device__ __forceinline__ void mma_bf16(float* c, const uint32_t* a,
                                         uint32_t b0, uint32_t b1) {
    asm volatile(
        "mma.sync.aligned.m16n8k16.row.col.f32.bf16.bf16.f32 "
        "{%0,%1,%2,%3}, {%4,%5,%6,%7}, {%8,%9}, {%0,%1,%2,%3};"
        : "+f"(c[0]), "+f"(c[1]), "+f"(c[2]), "+f"(c[3])
        : "r"(a[0]), "r"(a[1]), "r"(a[2]), "r"(a[3]), "r"(b0), "r"(b1));
}
__device__ __forceinline__ void mma_f16(float* c, const uint32_t* a,
                                        uint32_t b0, uint32_t b1) {
    asm volatile(
        "mma.sync.aligned.m16n8k16.row.col.f32.f16.f16.f32 "
        "{%0,%1,%2,%3}, {%4,%5,%6,%7}, {%8,%9}, {%0,%1,%2,%3};"
        : "+f"(c[0]), "+f"(c[1]), "+f"(c[2]), "+f"(c[3])
        : "r"(a[0]), "r"(a[1]), "r"(a[2]), "r"(a[3]), "r"(b0), "r"(b1));
}
__device__ __forceinline__ void cp16(uint32_t dst, const void* src) {
    asm volatile("cp.async.cg.shared.global [%0], [%1], 16;"
                 :: "r"(dst), "l"(src) : "memory");
}
#define CP_COMMIT() asm volatile("cp.async.commit_group;" ::: "memory")
#define CP_WAIT1()  asm volatile("cp.async.wait_group 1;" ::: "memory")
#define CP_WAIT0()  asm volatile("cp.async.wait_group 0;" ::: "memory")

__device__ __forceinline__ uint32_t pack_half(float lo, float hi) {
    uint32_t r;
    asm("cvt.rn.f16x2.f32 %0, %1, %2;" : "=r"(r) : "f"(hi), "f"(lo));
    return r;
}

// ---------------------------------------------------------------------------
// One-launch fp32 -> bf16 hi/lo split over all 7 inputs (grid.y = segment)
// ---------------------------------------------------------------------------
struct SplitArgs {
    const float* x[7];
    __nv_bfloat16* h[7];
    __nv_bfloat16* l[7];
    int n4[7];
};

__global__ void __launch_bounds__(256)
split_all(SplitArgs a)
{
    const int seg = blockIdx.y;
    const int i = blockIdx.x * 256 + threadIdx.x;
    if (i >= a.n4[seg]) return;
    float4 v = ((const float4*)a.x[seg])[i];
    __nv_bfloat16 h0 = __float2bfloat16(v.x), h1 = __float2bfloat16(v.y);
    __nv_bfloat16 h2 = __float2bfloat16(v.z), h3 = __float2bfloat16(v.w);
    float l0 = v.x - __bfloat162float(h0), l1 = v.y - __bfloat162float(h1);
    float l2 = v.z - __bfloat162float(h2), l3 = v.w - __bfloat162float(h3);
    uint2 hv, lv;
    hv.x = (uint32_t)__bfloat16_as_ushort(h0) | ((uint32_t)__bfloat16_as_ushort(h1) << 16);
    hv.y = (uint32_t)__bfloat16_as_ushort(h2) | ((uint32_t)__bfloat16_as_ushort(h3) << 16);
    lv.x = (uint32_t)__bfloat16_as_ushort(__float2bfloat16(l0)) |
           ((uint32_t)__bfloat16_as_ushort(__float2bfloat16(l1)) << 16);
    lv.y = (uint32_t)__bfloat16_as_ushort(__float2bfloat16(l2)) |
           ((uint32_t)__bfloat16_as_ushort(__float2bfloat16(l3)) << 16);
    ((uint2*)a.h[seg])[i] = hv;
    ((uint2*)a.l[seg])[i] = lv;
}

// ---------------------------------------------------------------------------
// mma.sync split-bf16 GEMM — EXACT R12 configuration (best known):
// KT=64, 4-plane stages, 96KB smem, no reg cap, 96 MMAs/sync.
// EPI 0: bias + fp16 hi/lo split store, ld 1024          [Q projection]
// EPI 1: bias + fp16 hi/lo split, transposed per-head    [V projection]
// EPI 2: bias + fp16 hi-only store, ld 1024              [K projection]
// EPI 4: bias + fp32 store, ld 1024                      [output projection]
// ---------------------------------------------------------------------------
#define MT 128
#define NT 64
#define KT 64
#define STG_STRIDE 49152
#define OFF_AH 0
#define OFF_AL 16384
#define OFF_BH 32768
#define OFF_BL 40960
#define SM_PIPE  98304

template <int EPI>
__global__ void __launch_bounds__(256)
mma_gemm(const __nv_bfloat16* __restrict__ Ah, const __nv_bfloat16* __restrict__ Al,
         const __nv_bfloat16* __restrict__ Bh, const __nv_bfloat16* __restrict__ Bl,
         const float* __restrict__ bias, float* __restrict__ outF,
         __half* __restrict__ outH, __half* __restrict__ outL,
         int K, int lda, int ldb)
{
    extern __shared__ uint8_t dsm[];
    const uint32_t sb = smem_u32(dsm);
    const int tid = threadIdx.x, wid = tid >> 5, lane = tid & 31;
    const int wm = wid >> 1, wn = wid & 1;
    const int n0 = blockIdx.x * NT, m0 = blockIdx.y * MT;

    float acc[2][4][4];
#pragma unroll
    for (int i = 0; i < 2; i++)
#pragma unroll
        for (int j = 0; j < 4; j++)
#pragma unroll
            for (int r = 0; r < 4; r++) acc[i][j][r] = 0.0f;

    const int lrow = lane & 15, lkh = lane >> 4;

    const int ntiles = K / KT;
    auto stage = [&](int kti, int buf) {
        const uint32_t b0 = sb + buf * STG_STRIDE;
        const int kt = kti * KT;
#pragma unroll
        for (int i = 0; i < 4; i++) {
            int chunk = tid + i * 256;
            int row = chunk >> 3, c16 = chunk & 7;
            long g = (long)(m0 + row) * lda + kt + c16 * 8;
            uint32_t so = SWZ((uint32_t)(row * 128 + c16 * 16));
            cp16(b0 + OFF_AH + so, Ah + g);
            cp16(b0 + OFF_AL + so, Al + g);
        }
#pragma unroll
        for (int i = 0; i < 2; i++) {
            int chunk = tid + i * 256;
            int row = chunk >> 3, c16 = chunk & 7;
            long g = (long)(n0 + row) * ldb + kt + c16 * 8;
            uint32_t so = SWZ((uint32_t)(row * 128 + c16 * 16));
            cp16(b0 + OFF_BH + so, Bh + g);
            if (EPI != 2) cp16(b0 + OFF_BL + so, Bl + g);
            else          cp16(b0 + OFF_BL + so, Bl + g);
        }
    };
    stage(0, 0);
    CP_COMMIT();
    for (int t = 0; t < ntiles; t++) {
        if (t + 1 < ntiles) { stage(t + 1, (t + 1) & 1); CP_COMMIT(); CP_WAIT1(); }
        else { CP_WAIT0(); }
        __syncthreads();
        const uint32_t b0 = sb + (t & 1) * STG_STRIDE;
#pragma unroll
        for (int ks = 0; ks < 4; ks++) {
            const uint32_t kb = ks * 32 + lkh * 16;
            uint32_t ah[2][4], al[2][4];
#pragma unroll
            for (int ms = 0; ms < 2; ms++) {
                uint32_t ro = (uint32_t)(wm * 32 + ms * 16 + lrow) * 128 + kb;
                ldsm_x4(ah[ms][0], ah[ms][1], ah[ms][2], ah[ms][3], b0 + OFF_AH + SWZ(ro));
                ldsm_x4(al[ms][0], al[ms][1], al[ms][2], al[ms][3], b0 + OFF_AL + SWZ(ro));
            }
            uint32_t bh[4][2], bl[4][2];
#pragma unroll
            for (int half = 0; half < 2; half++) {
                uint32_t ro = (uint32_t)(wn * 32 + half * 16 + lrow) * 128 + kb;
                uint32_t r0, r1, r2, r3;
                ldsm_x4(r0, r1, r2, r3, b0 + OFF_BH + SWZ(ro));
                bh[half * 2 + 0][0] = r0; bh[half * 2 + 0][1] = r2;
                bh[half * 2 + 1][0] = r1; bh[half * 2 + 1][1] = r3;
                ldsm_x4(r0, r1, r2, r3, b0 + OFF_BL + SWZ(ro));
                bl[half * 2 + 0][0] = r0; bl[half * 2 + 0][1] = r2;
                bl[half * 2 + 1][0] = r1; bl[half * 2 + 1][1] = r3;
            }
#pragma unroll
            for (int ms = 0; ms < 2; ms++)
#pragma unroll
                for (int nb = 0; nb < 4; nb++) {
                    mma_bf16(acc[ms][nb], ah[ms], bh[nb][0], bh[nb][1]);
                    mma_bf16(acc[ms][nb], al[ms], bh[nb][0], bh[nb][1]);
                    mma_bf16(acc[ms][nb], ah[ms], bl[nb][0], bl[nb][1]);
                }
        }
        __syncthreads();
    }

    // ---- epilogue: regs -> padded smem staging -> coalesced global ----
    float* st = (float*)dsm;                     // [128][65] fp32
    {
        const int lr = lane >> 2, lc = (lane & 3) * 2;
#pragma unroll
        for (int ms = 0; ms < 2; ms++)
#pragma unroll
            for (int nb = 0; nb < 4; nb++) {
                int r = wm * 32 + ms * 16 + lr;
                int c = wn * 32 + nb * 8 + lc;
                st[r * 65 + c]            = acc[ms][nb][0];
                st[r * 65 + c + 1]        = acc[ms][nb][1];
                st[(r + 8) * 65 + c]      = acc[ms][nb][2];
                st[(r + 8) * 65 + c + 1]  = acc[ms][nb][3];
            }
    }
    __syncthreads();

    if (EPI == 4) {            // OUT: fp32 + bias
        for (int i = tid; i < MT * NT; i += 256) {
            int row = i >> 6, c = i & 63;
            outF[(long)(m0 + row) * 1024 + n0 + c] = st[row * 65 + c] + bias[n0 + c];
        }
    } else if (EPI == 0) {     // Q: bias + fp16 hi/lo split
        for (int i = tid; i < MT * NT; i += 256) {
            int row = i >> 6, c = i & 63;
            float v = st[row * 65 + c] + bias[n0 + c];
            long o = (long)(m0 + row) * 1024 + n0 + c;
            __half h = __float2half_rn(v);
            outH[o] = h;
            outL[o] = __float2half_rn(v - __half2float(h));
        }
    } else if (EPI == 2) {     // K: bias + fp16 hi only
        for (int i = tid; i < MT * NT; i += 256) {
            int row = i >> 6, c = i & 63;
            float v = st[row * 65 + c] + bias[n0 + c];
            outH[(long)(m0 + row) * 1024 + n0 + c] = __float2half_rn(v);
        }
    } else {                   // V: bias + fp16 hi/lo, transposed [BH,64,S]
        for (int i = tid; i < MT * NT; i += 256) {
            int j = i >> 7, rl = i & 127;
            int r = m0 + rl, cg = n0 + j;
            float v = st[rl * 65 + j] + bias[cg];
            int b = r >> 11, s = r & 2047, hh = cg >> 6, jj = cg & 63;
            long o = ((long)(b * 16 + hh) * 64 + jj) * 2048 + s;
            __half h = __float2half_rn(v);
            outH[o] = h;
            outL[o] = __float2half_rn(v - __half2float(h));
        }
    }
    (void)outL;
}

// ---------------------------------------------------------------------------
// Fused scores + softmax + context — fp16.
// Pass A (NEW): 128 keys per pipeline step (two 64-key sub-tiles per sync,
//   one combined reduction) — doubles MMAs-per-sync, halves barrier count.
// Pass B: 2-pass S (qh*kh + ql*kh), normalize, store attn once,
//         P -> fp16 plane, O += P @ (Vh + Vl), cross-wn reduce, bf16 ctx.
// ---------------------------------------------------------------------------
#define FB_QH   0
#define FB_QL   16384
#define FB_ST0  32768
#define FB_STRIDE 32768
#define FB_PART 98304           // float[2][128]
#define FB_ROWL 99328           // float[128]
#define FB_SM   99840

__global__ void __launch_bounds__(256)
fused_attn_k(const __half* __restrict__ qh, const __half* __restrict__ ql,
             const __half* __restrict__ kh,
             const __half* __restrict__ vth, const __half* __restrict__ vtl,
             float* __restrict__ attn,
             __nv_bfloat16* __restrict__ ch, __nv_bfloat16* __restrict__ cl)
{
    extern __shared__ uint8_t dsm[];
    const uint32_t sb = smem_u32(dsm);
    const int tid = threadIdx.x, wid = tid >> 5, lane = tid & 31;
    const int wm = wid >> 1, wn = wid & 1;
    const int lrow = lane & 15, lkh = lane >> 4;
    const int lr = lane >> 2, lc = lane & 3;
    const int m0 = blockIdx.x * 128;
    const int z = blockIdx.y;
    const long base = (long)(z >> 4) * 2048L * 1024 + (long)(z & 15) * 64;
    const __half* qh_h = qh + base;
    const __half* ql_h = ql + base;
    const __half* kh_h = kh + base;
    const __half* vh_h = vth + (long)z * 64L * 2048;
    const __half* vl_h = vtl + (long)z * 64L * 2048;

    float* part  = (float*)(dsm + FB_PART);
    float* row_l = (float*)(dsm + FB_ROWL);

    // Pass A staging: 128 keys (16KB) per step
    auto stage_k128 = [&](int t, int buf) {
        const uint32_t sd = sb + FB_ST0 + buf * FB_STRIDE;
#pragma unroll
        for (int i = 0; i < 4; i++) {
            int chunk = tid + i * 256;               // 1024: 128 rows x 8
            int row = chunk >> 3, c16 = chunk & 7;
            long g = (long)(t * 128 + row) * 1024 + c16 * 8;
            uint32_t so = SWZ((uint32_t)(row * 128 + c16 * 16));
            cp16(sd + so, kh_h + g);
        }
    };
    // Pass B staging: K hi 8K + V hi 8K + V lo 8K
    auto stage_kv = [&](int t, int buf) {
        const uint32_t sd = sb + FB_ST0 + buf * FB_STRIDE;
#pragma unroll
        for (int i = 0; i < 2; i++) {
            int chunk = tid + i * 256;
            int row = chunk >> 3, c16 = chunk & 7;
            long g = (long)(t * 64 + row) * 1024 + c16 * 8;
            uint32_t so = SWZ((uint32_t)(row * 128 + c16 * 16));
            cp16(sd + so, kh_h + g);
        }
#pragma unroll
        for (int i = 0; i < 2; i++) {
            int chunk = tid + i * 256;               // row = dk 0..63
            int row = chunk >> 3, c16 = chunk & 7;
            long g = (long)row * 2048 + t * 64 + c16 * 8;
            uint32_t so = SWZ((uint32_t)(row * 128 + c16 * 16));
            cp16(sd + 8192 + so, vh_h + g);
            cp16(sd + 16384 + so, vl_h + g);
        }
    };

    // S tile, 1-pass (pass A), from explicit smem base
    auto compute_tile_hi = [&](uint32_t kbase, float acc[2][4][4]) {
#pragma unroll
        for (int i = 0; i < 2; i++)
#pragma unroll
            for (int j = 0; j < 4; j++)
#pragma unroll
                for (int r = 0; r < 4; r++) acc[i][j][r] = 0.0f;
#pragma unroll
        for (int ks = 0; ks < 4; ks++) {
            const uint32_t kb = ks * 32 + lkh * 16;
            uint32_t ah[2][4];
#pragma unroll
            for (int ms = 0; ms < 2; ms++) {
                uint32_t ro = (uint32_t)(wm * 32 + ms * 16 + lrow) * 128 + kb;
                ldsm_x4(ah[ms][0], ah[ms][1], ah[ms][2], ah[ms][3], sb + FB_QH + SWZ(ro));
            }
            uint32_t bh[4][2];
#pragma unroll
            for (int half = 0; half < 2; half++) {
                uint32_t ro = (uint32_t)(wn * 32 + half * 16 + lrow) * 128 + kb;
                uint32_t r0, r1, r2, r3;
                ldsm_x4(r0, r1, r2, r3, kbase + SWZ(ro));
                bh[half * 2 + 0][0] = r0; bh[half * 2 + 0][1] = r2;
                bh[half * 2 + 1][0] = r1; bh[half * 2 + 1][1] = r3;
            }
#pragma unroll
            for (int ms = 0; ms < 2; ms++)
#pragma unroll
                for (int nb = 0; nb < 4; nb++)
                    mma_f16(acc[ms][nb], ah[ms], bh[nb][0], bh[nb][1]);
        }
    };
    // S tile, 2-pass (pass B)
    auto compute_tile = [&](int buf, float acc[2][4][4]) {
#pragma unroll
        for (int i = 0; i < 2; i++)
#pragma unroll
            for (int j = 0; j < 4; j++)
#pragma unroll
                for (int r = 0; r < 4; r++) acc[i][j][r] = 0.0f;
        const uint32_t kbh = sb + FB_ST0 + buf * FB_STRIDE;
#pragma unroll
        for (int ks = 0; ks < 4; ks++) {
            const uint32_t kb = ks * 32 + lkh * 16;
            uint32_t ah[2][4], al[2][4];
#pragma unroll
            for (int ms = 0; ms < 2; ms++) {
                uint32_t ro = (uint32_t)(wm * 32 + ms * 16 + lrow) * 128 + kb;
                ldsm_x4(ah[ms][0], ah[ms][1], ah[ms][2], ah[ms][3], sb + FB_QH + SWZ(ro));
                ldsm_x4(al[ms][0], al[ms][1], al[ms][2], al[ms][3], sb + FB_QL + SWZ(ro));
            }
            uint32_t bh[4][2];
#pragma unroll
            for (int half = 0; half < 2; half++) {
                uint32_t ro = (uint32_t)(wn * 32 + half * 16 + lrow) * 128 + kb;
                uint32_t r0, r1, r2, r3;
                ldsm_x4(r0, r1, r2, r3, kbh + SWZ(ro));
                bh[half * 2 + 0][0] = r0; bh[half * 2 + 0][1] = r2;
                bh[half * 2 + 1][0] = r1; bh[half * 2 + 1][1] = r3;
            }
#pragma unroll
            for (int ms = 0; ms < 2; ms++)
#pragma unroll
                for (int nb = 0; nb < 4; nb++) {
                    mma_f16(acc[ms][nb], ah[ms], bh[nb][0], bh[nb][1]);
                    mma_f16(acc[ms][nb], al[ms], bh[nb][0], bh[nb][1]);
                }
        }
    };

    // ---- prologue: q tile + first 128-key K block ----
#pragma unroll
    for (int i = 0; i < 4; i++) {
        int chunk = tid + i * 256;
        int row = chunk >> 3, c16 = chunk & 7;
        long g = (long)(m0 + row) * 1024 + c16 * 8;
        uint32_t so = SWZ((uint32_t)(row * 128 + c16 * 16));
        cp16(sb + FB_QH + so, qh_h + g);
        cp16(sb + FB_QL + so, ql_h + g);
    }
    if (tid < 128) row_l[tid] = 0.0f;
    stage_k128(0, 0);
    CP_COMMIT();

    float acc[2][4][4];

    // ---- pass A: 16 steps x 128 keys; one reduction per step ----
    for (int t = 0; t < 16; t++) {
        if (t + 1 < 16) { stage_k128(t + 1, (t + 1) & 1); CP_COMMIT(); CP_WAIT1(); }
        else { CP_WAIT0(); }
        __syncthreads();
        const uint32_t kb0 = sb + FB_ST0 + (t & 1) * FB_STRIDE;
        float s0a[2] = {0.0f, 0.0f}, s1a[2] = {0.0f, 0.0f};
#pragma unroll
        for (int sub = 0; sub < 2; sub++) {
            compute_tile_hi(kb0 + sub * 8192, acc);
#pragma unroll
            for (int ms = 0; ms < 2; ms++) {
#pragma unroll
                for (int nb = 0; nb < 4; nb++) {
                    s0a[ms] += __expf(acc[ms][nb][0] * 0.125f) + __expf(acc[ms][nb][1] * 0.125f);
                    s1a[ms] += __expf(acc[ms][nb][2] * 0.125f) + __expf(acc[ms][nb][3] * 0.125f);
                }
            }
        }
#pragma unroll
        for (int ms = 0; ms < 2; ms++) {
            float s0 = s0a[ms], s1 = s1a[ms];
            s0 += __shfl_xor_sync(0xffffffffu, s0, 1);
            s0 += __shfl_xor_sync(0xffffffffu, s0, 2);
            s1 += __shfl_xor_sync(0xffffffffu, s1, 1);
            s1 += __shfl_xor_sync(0xffffffffu, s1, 2);
            if (lc == 0) {
                part[wn * 128 + wm * 32 + ms * 16 + lr]     = s0;
                part[wn * 128 + wm * 32 + ms * 16 + 8 + lr] = s1;
            }
        }
        __syncthreads();
        if (tid < 128) row_l[tid] += part[tid] + part[128 + tid];
    }
    __syncthreads();
    float inv[2][2];
#pragma unroll
    for (int ms = 0; ms < 2; ms++) {
        inv[ms][0] = 1.0f / row_l[wm * 32 + ms * 16 + lr];
        inv[ms][1] = 1.0f / row_l[wm * 32 + ms * 16 + 8 + lr];
    }

    float accO[2][8][4];
#pragma unroll
    for (int ms = 0; ms < 2; ms++)
#pragma unroll
        for (int dn = 0; dn < 8; dn++)
#pragma unroll
            for (int r = 0; r < 4; r++) accO[ms][dn][r] = 0.0f;

    // ---- pass B: 2-pass S, normalize, store attn, O += P @ (Vh + Vl) ----
    stage_kv(0, 0);
    CP_COMMIT();
    for (int t = 0; t < 32; t++) {
        if (t + 1 < 32) { stage_kv(t + 1, (t + 1) & 1); CP_COMMIT(); CP_WAIT1(); }
        else { CP_WAIT0(); }
        __syncthreads();
        compute_tile(t & 1, acc);

#pragma unroll
        for (int ms = 0; ms < 2; ms++)
#pragma unroll
            for (int nb = 0; nb < 4; nb++) {
                acc[ms][nb][0] = __expf(acc[ms][nb][0] * 0.125f) * inv[ms][0];
                acc[ms][nb][1] = __expf(acc[ms][nb][1] * 0.125f) * inv[ms][0];
                acc[ms][nb][2] = __expf(acc[ms][nb][2] * 0.125f) * inv[ms][1];
                acc[ms][nb][3] = __expf(acc[ms][nb][3] * 0.125f) * inv[ms][1];
            }

        const int colb = t * 64 + wn * 32 + lc * 2;
#pragma unroll
        for (int ms = 0; ms < 2; ms++) {
            long rb0 = ((long)z * 2048 + m0 + wm * 32 + ms * 16 + lr) * 2048;
            long rb1 = rb0 + 8L * 2048;
#pragma unroll
            for (int nb = 0; nb < 4; nb++) {
                *(float2*)(attn + rb0 + colb + nb * 8) =
                    make_float2(acc[ms][nb][0], acc[ms][nb][1]);
                *(float2*)(attn + rb1 + colb + nb * 8) =
                    make_float2(acc[ms][nb][2], acc[ms][nb][3]);
            }
        }

        // O += P @ (Vh + Vl)
        const uint32_t vbh = sb + FB_ST0 + (t & 1) * FB_STRIDE + 8192;
        const uint32_t vbl = vbh + 8192;
#pragma unroll
        for (int kh2 = 0; kh2 < 2; kh2++) {
            uint32_t vh[8][2], vl[8][2];
#pragma unroll
            for (int dh = 0; dh < 4; dh++) {
                uint32_t ro = (uint32_t)(dh * 16 + lrow) * 128 +
                              (uint32_t)(wn * 32 + kh2 * 16) * 2 + lkh * 16;
                uint32_t r0, r1, r2, r3;
                ldsm_x4(r0, r1, r2, r3, vbh + SWZ(ro));
                vh[dh * 2 + 0][0] = r0; vh[dh * 2 + 0][1] = r2;
                vh[dh * 2 + 1][0] = r1; vh[dh * 2 + 1][1] = r3;
                ldsm_x4(r0, r1, r2, r3, vbl + SWZ(ro));
                vl[dh * 2 + 0][0] = r0; vl[dh * 2 + 0][1] = r2;
                vl[dh * 2 + 1][0] = r1; vl[dh * 2 + 1][1] = r3;
            }
#pragma unroll
            for (int ms = 0; ms < 2; ms++) {
                const float* c0 = acc[ms][2 * kh2];
                const float* c1 = acc[ms][2 * kh2 + 1];
                uint32_t ph[4];
                ph[0] = pack_half(c0[0], c0[1]);
                ph[1] = pack_half(c0[2], c0[3]);
                ph[2] = pack_half(c1[0], c1[1]);
                ph[3] = pack_half(c1[2], c1[3]);
#pragma unroll
                for (int dn = 0; dn < 8; dn++) {
                    mma_f16(accO[ms][dn], ph, vh[dn][0], vh[dn][1]);
                    mma_f16(accO[ms][dn], ph, vl[dn][0], vl[dn][1]);
                }
            }
        }
        __syncthreads();
    }

    // ---- ctx epilogue: cross-wn reduce in smem, bf16 split store [B,S,D] ----
    float* st = (float*)dsm;
    {
        const int lc2 = lc * 2;
        if (wn == 0) {
#pragma unroll
            for (int ms = 0; ms < 2; ms++)
#pragma unroll
                for (int dn = 0; dn < 8; dn++) {
                    int r = wm * 32 + ms * 16 + lr;
                    int c = dn * 8 + lc2;
                    st[r * 65 + c]           = accO[ms][dn][0];
                    st[r * 65 + c + 1]       = accO[ms][dn][1];
                    st[(r + 8) * 65 + c]     = accO[ms][dn][2];
                    st[(r + 8) * 65 + c + 1] = accO[ms][dn][3];
                }
        }
        __syncthreads();
        if (wn == 1) {
#pragma unroll
            for (int ms = 0; ms < 2; ms++)
#pragma unroll
                for (int dn = 0; dn < 8; dn++) {
                    int r = wm * 32 + ms * 16 + lr;
                    int c = dn * 8 + lc2;
                    st[r * 65 + c]           += accO[ms][dn][0];
                    st[r * 65 + c + 1]       += accO[ms][dn][1];
                    st[(r + 8) * 65 + c]     += accO[ms][dn][2];
                    st[(r + 8) * 65 + c + 1] += accO[ms][dn][3];
                }
        }
        __syncthreads();
    }
    {
        const int b = z >> 4, hh = z & 15;
        for (int i = tid; i < 128 * 64; i += 256) {
            int row = i >> 6, c = i & 63;
            float v = st[row * 65 + c];
            long o = (long)((b << 11) + m0 + row) * 1024 + hh * 64 + c;
            __nv_bfloat16 h = __float2bfloat16(v);
            ch[o] = h;
            cl[o] = __float2bfloat16(v - __bfloat162float(h));
        }
    }
}

// ---------------------------------------------------------------------------
extern "C" void kernel_launch(void* const* d_in, const int* in_sizes, int n_in,
                              void* d_out, int out_size)
{
    const float* Q  = (const float*)d_in[0];
    const float* K  = (const float*)d_in[1];
    const float* V  = (const float*)d_in[2];
    const float* Wq = (const float*)d_in[3];
    const float* bq = (const float*)d_in[4];
    const float* Wk = (const float*)d_in[5];
    const float* bk = (const float*)d_in[6];
    const float* Wv = (const float*)d_in[7];
    const float* bv = (const float*)d_in[8];
    const float* Wo = (const float*)d_in[9];
    const float* bo = (const float*)d_in[10];
    float* out = (float*)d_out;

    __nv_bfloat16 *Qh, *Ql, *Kh, *Kl, *Vh, *Vl;
    __nv_bfloat16 *Wqh, *Wql, *Wkh, *Wkl, *Wvh, *Wvl, *Woh, *Wol;
    __half *qh, *ql, *kh, *vth, *vtl;
    __nv_bfloat16 *ch, *cl;
    float* attn_scratch;
    cudaGetSymbolAddress((void**)&Qh, g_Qh);   cudaGetSymbolAddress((void**)&Ql, g_Ql);
    cudaGetSymbolAddress((void**)&Kh, g_Kh);   cudaGetSymbolAddress((void**)&Kl, g_Kl);
    cudaGetSymbolAddress((void**)&Vh, g_Vh);   cudaGetSymbolAddress((void**)&Vl, g_Vl);
    cudaGetSymbolAddress((void**)&Wqh, g_Wqh); cudaGetSymbolAddress((void**)&Wql, g_Wql);
    cudaGetSymbolAddress((void**)&Wkh, g_Wkh); cudaGetSymbolAddress((void**)&Wkl, g_Wkl);
    cudaGetSymbolAddress((void**)&Wvh, g_Wvh); cudaGetSymbolAddress((void**)&Wvl, g_Wvl);
    cudaGetSymbolAddress((void**)&Woh, g_Woh); cudaGetSymbolAddress((void**)&Wol, g_Wol);
    cudaGetSymbolAddress((void**)&qh, g_qh);   cudaGetSymbolAddress((void**)&ql, g_ql);
    cudaGetSymbolAddress((void**)&kh, g_kh);
    cudaGetSymbolAddress((void**)&vth, g_vth); cudaGetSymbolAddress((void**)&vtl, g_vtl);
    cudaGetSymbolAddress((void**)&ch, g_ch);   cudaGetSymbolAddress((void**)&cl, g_cl);
    cudaGetSymbolAddress((void**)&attn_scratch, g_attn);

    float* attn = ((long)out_size >= OUT_TOTAL) ? (out + OUT0) : attn_scratch;

    cudaFuncSetAttribute(mma_gemm<0>, cudaFuncAttributeMaxDynamicSharedMemorySize, SM_PIPE);
    cudaFuncSetAttribute(mma_gemm<1>, cudaFuncAttributeMaxDynamicSharedMemorySize, SM_PIPE);
    cudaFuncSetAttribute(mma_gemm<2>, cudaFuncAttributeMaxDynamicSharedMemorySize, SM_PIPE);
    cudaFuncSetAttribute(mma_gemm<4>, cudaFuncAttributeMaxDynamicSharedMemorySize, SM_PIPE);
    cudaFuncSetAttribute(fused_attn_k, cudaFuncAttributeMaxDynamicSharedMemorySize, FB_SM);

    // 0) One-launch split of all 7 fp32 inputs into bf16 hi/lo
    {
        SplitArgs a;
        a.x[0] = Q;  a.h[0] = Qh;  a.l[0] = Ql;  a.n4[0] = TOKENS * DMODEL / 4;
        a.x[1] = K;  a.h[1] = Kh;  a.l[1] = Kl;  a.n4[1] = TOKENS * DMODEL / 4;
        a.x[2] = V;  a.h[2] = Vh;  a.l[2] = Vl;  a.n4[2] = TOKENS * DMODEL / 4;
        a.x[3] = Wq; a.h[3] = Wqh; a.l[3] = Wql; a.n4[3] = DMODEL * DMODEL / 4;
        a.x[4] = Wk; a.h[4] = Wkh; a.l[4] = Wkl; a.n4[4] = DMODEL * DMODEL / 4;
        a.x[5] = Wv; a.h[5] = Wvh; a.l[5] = Wvl; a.n4[5] = DMODEL * DMODEL / 4;
        a.x[6] = Wo; a.h[6] = Woh; a.l[6] = Wol; a.n4[6] = DMODEL * DMODEL / 4;
        dim3 gs((TOKENS * DMODEL / 4 + 255) / 256, 7, 1);
        split_all<<<gs, 256>>>(a);
    }

    // 1-3) Projections (bf16 3-pass, R12 config): Q->hi/lo, K->hi, V->hi/lo^T
    dim3 gp(DMODEL / NT, TOKENS / MT, 1);                       // (16, 32)
    mma_gemm<0><<<gp, 256, SM_PIPE>>>(Qh, Ql, Wqh, Wql, bq, nullptr, qh, ql,
                                      DMODEL, DMODEL, DMODEL);
    mma_gemm<2><<<gp, 256, SM_PIPE>>>(Kh, Kl, Wkh, Wkl, bk, nullptr, kh, nullptr,
                                      DMODEL, DMODEL, DMODEL);
    mma_gemm<1><<<gp, 256, SM_PIPE>>>(Vh, Vl, Wvh, Wvl, bv, nullptr, vth, vtl,
                                      DMODEL, DMODEL, DMODEL);

    // 4) Fused scores + softmax + context (dense pass A, 2-pass S, 2-pass O)
    dim3 gf(SEQ / 128, BH, 1);                                  // (16, 32)
    fused_attn_k<<<gf, 256, FB_SM>>>(qh, ql, kh, vth, vtl, attn, ch, cl);

    // 5) Output projection: ctx @ Wo^T + bo -> out fp32 (bf16 3-pass)
    mma_gemm<4><<<gp, 256, SM_PIPE>>>(ch, cl, Woh, Wol, bo, out, nullptr, nullptr,
                                      DMODEL, DMODEL, DMODEL);

    (void)n_in; (void)in_sizes;
}

// round 16
// speedup vs baseline: 1.2036x; 1.0391x over previous
#include <cuda_runtime.h>
#include <cuda_bf16.h>
#include <cuda_fp16.h>
#include <cstdint>

// ---------------------------------------------------------------------------
// Problem constants
// ---------------------------------------------------------------------------
#define BATCH   2
#define SEQ     2048
#define DMODEL  1024
#define NHEAD   16
#define DK      64
#define BH      (BATCH * NHEAD)              // 32
#define TOKENS  (BATCH * SEQ)                // 4096
#define OUT0    (TOKENS * DMODEL)            // 4,194,304
#define ATTN_N  ((long)BH * SEQ * SEQ)       // 134,217,728
#define OUT_TOTAL (OUT0 + ATTN_N)

// ---------------------------------------------------------------------------
// Scratch (static device arrays; no cudaMalloc anywhere)
// ---------------------------------------------------------------------------
__device__ __nv_bfloat16 g_Qh[TOKENS * DMODEL], g_Ql[TOKENS * DMODEL];
__device__ __nv_bfloat16 g_Kh[TOKENS * DMODEL], g_Kl[TOKENS * DMODEL];
__device__ __nv_bfloat16 g_Vh[TOKENS * DMODEL], g_Vl[TOKENS * DMODEL];
__device__ __nv_bfloat16 g_Wqh[DMODEL * DMODEL], g_Wql[DMODEL * DMODEL];
__device__ __nv_bfloat16 g_Wkh[DMODEL * DMODEL], g_Wkl[DMODEL * DMODEL];
__device__ __nv_bfloat16 g_Wvh[DMODEL * DMODEL], g_Wvl[DMODEL * DMODEL];
__device__ __nv_bfloat16 g_Woh[DMODEL * DMODEL], g_Wol[DMODEL * DMODEL];
__device__ __half g_qh[TOKENS * DMODEL], g_ql[TOKENS * DMODEL];     // fp16
__device__ __half g_kh[TOKENS * DMODEL];                             // fp16 (hi only)
__device__ __half g_vth[BH * DK * SEQ], g_vtl[BH * DK * SEQ];        // fp16 V^T hi/lo
__device__ __nv_bfloat16 g_ch[TOKENS * DMODEL], g_cl[TOKENS * DMODEL];  // ctx bf16
__device__ float g_attn[ATTN_N];                 // fallback if d_out lacks attn

// ---------------------------------------------------------------------------
// Helpers
// ---------------------------------------------------------------------------
__device__ __forceinline__ uint32_t smem_u32(const void* p) {
    uint32_t a;
    asm("{ .reg .u64 t; cvta.to.shared.u64 t, %1; cvt.u32.u64 %0, t; }"
        : "=r"(a) : "l"(p));
    return a;
}
#define SWZ(off) ((off) ^ (((off) >> 3) & 0x70))

__device__ __forceinline__ void ldsm_x4(uint32_t& r0, uint32_t& r1,
                                        uint32_t& r2, uint32_t& r3, uint32_t a) {
    asm volatile("ldmatrix.sync.aligned.m8n8.x4.shared.b16 {%0,%1,%2,%3}, [%4];"
                 : "=r"(r0), "=r"(r1), "=r"(r2), "=r"(r3) : "r"(a));
}
__device__ __forceinline__ void mma_bf16(float* c, const uint32_t* a,
                                         uint32_t b0, uint32_t b1) {
    asm volatile(
        "mma.sync.aligned.m16n8k16.row.col.f32.bf16.bf16.f32 "
        "{%0,%1,%2,%3}, {%4,%5,%6,%7}, {%8,%9}, {%0,%1,%2,%3};"
        : "+f"(c[0]), "+f"(c[1]), "+f"(c[2]), "+f"(c[3])
        : "r"(a[0]), "r"(a[1]), "r"(a[2]), "r"(a[3]), "r"(b0), "r"(b1));
}
__device__ __forceinline__ void mma_f16(float* c, const uint32_t* a,
                                        uint32_t b0, uint32_t b1) {
    asm volatile(
        "mma.sync.aligned.m16n8k16.row.col.f32.f16.f16.f32 "
        "{%0,%1,%2,%3}, {%4,%5,%6,%7}, {%8,%9}, {%0,%1,%2,%3};"
        : "+f"(c[0]), "+f"(c[1]), "+f"(c[2]), "+f"(c[3])
        : "r"(a[0]), "r"(a[1]), "r"(a[2]), "r"(a[3]), "r"(b0), "r"(b1));
}
__device__ __forceinline__ void cp16(uint32_t dst, const void* src) {
    asm volatile("cp.async.cg.shared.global [%0], [%1], 16;"
                 :: "r"(dst), "l"(src) : "memory");
}
#define CP_COMMIT() asm volatile("cp.async.commit_group;" ::: "memory")
#define CP_WAIT1()  asm volatile("cp.async.wait_group 1;" ::: "memory")
#define CP_WAIT0()  asm volatile("cp.async.wait_group 0;" ::: "memory")

__device__ __forceinline__ uint32_t pack_half(float lo, float hi) {
    uint32_t r;
    asm("cvt.rn.f16x2.f32 %0, %1, %2;" : "=r"(r) : "f"(hi), "f"(lo));
    return r;
}

// ---------------------------------------------------------------------------
// One-launch fp32 -> bf16 hi/lo split over all 7 inputs (grid.y = segment)
// ---------------------------------------------------------------------------
struct SplitArgs {
    const float* x[7];
    __nv_bfloat16* h[7];
    __nv_bfloat16* l[7];
    int n4[7];
};

__global__ void __launch_bounds__(256)
split_all(SplitArgs a)
{
    const int seg = blockIdx.y;
    const int i = blockIdx.x * 256 + threadIdx.x;
    if (i >= a.n4[seg]) return;
    float4 v = ((const float4*)a.x[seg])[i];
    __nv_bfloat16 h0 = __float2bfloat16(v.x), h1 = __float2bfloat16(v.y);
    __nv_bfloat16 h2 = __float2bfloat16(v.z), h3 = __float2bfloat16(v.w);
    float l0 = v.x - __bfloat162float(h0), l1 = v.y - __bfloat162float(h1);
    float l2 = v.z - __bfloat162float(h2), l3 = v.w - __bfloat162float(h3);
    uint2 hv, lv;
    hv.x = (uint32_t)__bfloat16_as_ushort(h0) | ((uint32_t)__bfloat16_as_ushort(h1) << 16);
    hv.y = (uint32_t)__bfloat16_as_ushort(h2) | ((uint32_t)__bfloat16_as_ushort(h3) << 16);
    lv.x = (uint32_t)__bfloat16_as_ushort(__float2bfloat16(l0)) |
           ((uint32_t)__bfloat16_as_ushort(__float2bfloat16(l1)) << 16);
    lv.y = (uint32_t)__bfloat16_as_ushort(__float2bfloat16(l2)) |
           ((uint32_t)__bfloat16_as_ushort(__float2bfloat16(l3)) << 16);
    ((uint2*)a.h[seg])[i] = hv;
    ((uint2*)a.l[seg])[i] = lv;
}

// ---------------------------------------------------------------------------
// GEMM mainloop config (R12/R15 proven optimum): KT=64, 4 planes, 96KB,
// no reg cap, 96 MMAs/sync, M=128 x N=64 tile, 8 warps (4x2), 32x32/warp.
// ---------------------------------------------------------------------------
#define MT 128
#define NT 64
#define KT 64
#define STG_STRIDE 49152
#define OFF_AH 0
#define OFF_AL 16384
#define OFF_BH 32768
#define OFF_BL 40960
#define SM_PIPE  98304

// Shared mainloop: 3-pass split-bf16, cp.async 2-stage. Result in acc.
struct GemmCtx {
    uint32_t sb; int tid, lane, wm, wn, lrow, lkh, n0, m0;
};

__device__ __forceinline__ void gemm_mainloop(
    const GemmCtx& g, uint8_t* dsm,
    const __nv_bfloat16* __restrict__ Ah, const __nv_bfloat16* __restrict__ Al,
    const __nv_bfloat16* __restrict__ Bh, const __nv_bfloat16* __restrict__ Bl,
    int K, int lda, int ldb, float acc[2][4][4])
{
#pragma unroll
    for (int i = 0; i < 2; i++)
#pragma unroll
        for (int j = 0; j < 4; j++)
#pragma unroll
            for (int r = 0; r < 4; r++) acc[i][j][r] = 0.0f;

    const int ntiles = K / KT;
    auto stage = [&](int kti, int buf) {
        const uint32_t b0 = g.sb + buf * STG_STRIDE;
        const int kt = kti * KT;
#pragma unroll
        for (int i = 0; i < 4; i++) {
            int chunk = g.tid + i * 256;
            int row = chunk >> 3, c16 = chunk & 7;
            long gg = (long)(g.m0 + row) * lda + kt + c16 * 8;
            uint32_t so = SWZ((uint32_t)(row * 128 + c16 * 16));
            cp16(b0 + OFF_AH + so, Ah + gg);
            cp16(b0 + OFF_AL + so, Al + gg);
        }
#pragma unroll
        for (int i = 0; i < 2; i++) {
            int chunk = g.tid + i * 256;
            int row = chunk >> 3, c16 = chunk & 7;
            long gg = (long)(g.n0 + row) * ldb + kt + c16 * 8;
            uint32_t so = SWZ((uint32_t)(row * 128 + c16 * 16));
            cp16(b0 + OFF_BH + so, Bh + gg);
            cp16(b0 + OFF_BL + so, Bl + gg);
        }
    };
    stage(0, 0);
    CP_COMMIT();
    for (int t = 0; t < ntiles; t++) {
        if (t + 1 < ntiles) { stage(t + 1, (t + 1) & 1); CP_COMMIT(); CP_WAIT1(); }
        else { CP_WAIT0(); }
        __syncthreads();
        const uint32_t b0 = g.sb + (t & 1) * STG_STRIDE;
#pragma unroll
        for (int ks = 0; ks < 4; ks++) {
            const uint32_t kb = ks * 32 + g.lkh * 16;
            uint32_t ah[2][4], al[2][4];
#pragma unroll
            for (int ms = 0; ms < 2; ms++) {
                uint32_t ro = (uint32_t)(g.wm * 32 + ms * 16 + g.lrow) * 128 + kb;
                ldsm_x4(ah[ms][0], ah[ms][1], ah[ms][2], ah[ms][3], b0 + OFF_AH + SWZ(ro));
                ldsm_x4(al[ms][0], al[ms][1], al[ms][2], al[ms][3], b0 + OFF_AL + SWZ(ro));
            }
            uint32_t bh[4][2], bl[4][2];
#pragma unroll
            for (int half = 0; half < 2; half++) {
                uint32_t ro = (uint32_t)(g.wn * 32 + half * 16 + g.lrow) * 128 + kb;
                uint32_t r0, r1, r2, r3;
                ldsm_x4(r0, r1, r2, r3, b0 + OFF_BH + SWZ(ro));
                bh[half * 2 + 0][0] = r0; bh[half * 2 + 0][1] = r2;
                bh[half * 2 + 1][0] = r1; bh[half * 2 + 1][1] = r3;
                ldsm_x4(r0, r1, r2, r3, b0 + OFF_BL + SWZ(ro));
                bl[half * 2 + 0][0] = r0; bl[half * 2 + 0][1] = r2;
                bl[half * 2 + 1][0] = r1; bl[half * 2 + 1][1] = r3;
            }
#pragma unroll
            for (int ms = 0; ms < 2; ms++)
#pragma unroll
                for (int nb = 0; nb < 4; nb++) {
                    mma_bf16(acc[ms][nb], ah[ms], bh[nb][0], bh[nb][1]);
                    mma_bf16(acc[ms][nb], al[ms], bh[nb][0], bh[nb][1]);
                    mma_bf16(acc[ms][nb], ah[ms], bl[nb][0], bl[nb][1]);
                }
        }
        __syncthreads();
    }
}

// Stage accumulators into padded smem for coalesced epilogues.
__device__ __forceinline__ void stage_acc(uint8_t* dsm, const GemmCtx& g,
                                          float acc[2][4][4])
{
    float* st = (float*)dsm;                     // [128][65]
    const int lr = g.lane >> 2, lc = (g.lane & 3) * 2;
#pragma unroll
    for (int ms = 0; ms < 2; ms++)
#pragma unroll
        for (int nb = 0; nb < 4; nb++) {
            int r = g.wm * 32 + ms * 16 + lr;
            int c = g.wn * 32 + nb * 8 + lc;
            st[r * 65 + c]            = acc[ms][nb][0];
            st[r * 65 + c + 1]        = acc[ms][nb][1];
            st[(r + 8) * 65 + c]      = acc[ms][nb][2];
            st[(r + 8) * 65 + c + 1]  = acc[ms][nb][3];
        }
    __syncthreads();
}

// ---------------------------------------------------------------------------
// Merged Q/K/V projection kernel: grid.z selects the projection.
// z=0: Q -> fp16 hi/lo [B,S,HD];  z=1: K -> fp16 hi only;
// z=2: V -> fp16 hi/lo transposed per-head [BH,64,S].
// ---------------------------------------------------------------------------
struct ProjArgs {
    const __nv_bfloat16 *Ah[3], *Al[3], *Bh[3], *Bl[3];
    const float* bias[3];
    __half *outH[3], *outL[3];
};

__global__ void __launch_bounds__(256)
mma_proj3(ProjArgs pa)
{
    extern __shared__ uint8_t dsm[];
    const int z = blockIdx.z;
    GemmCtx g;
    g.sb = smem_u32(dsm);
    g.tid = threadIdx.x; g.lane = g.tid & 31;
    int wid = g.tid >> 5; g.wm = wid >> 1; g.wn = wid & 1;
    g.lrow = g.lane & 15; g.lkh = g.lane >> 4;
    g.n0 = blockIdx.x * NT; g.m0 = blockIdx.y * MT;

    float acc[2][4][4];
    gemm_mainloop(g, dsm, pa.Ah[z], pa.Al[z], pa.Bh[z], pa.Bl[z],
                  DMODEL, DMODEL, DMODEL, acc);
    stage_acc(dsm, g, acc);

    const float* st = (const float*)dsm;
    const float* bias = pa.bias[z];
    __half* outH = pa.outH[z];
    __half* outL = pa.outL[z];

    if (z == 0) {            // Q: bias + fp16 hi/lo split, ld 1024
        for (int i = g.tid; i < MT * NT; i += 256) {
            int row = i >> 6, c = i & 63;
            float v = st[row * 65 + c] + bias[g.n0 + c];
            long o = (long)(g.m0 + row) * 1024 + g.n0 + c;
            __half h = __float2half_rn(v);
            outH[o] = h;
            outL[o] = __float2half_rn(v - __half2float(h));
        }
    } else if (z == 1) {     // K: bias + fp16 hi only
        for (int i = g.tid; i < MT * NT; i += 256) {
            int row = i >> 6, c = i & 63;
            float v = st[row * 65 + c] + bias[g.n0 + c];
            outH[(long)(g.m0 + row) * 1024 + g.n0 + c] = __float2half_rn(v);
        }
    } else {                 // V: bias + fp16 hi/lo, transposed [BH,64,S]
        for (int i = g.tid; i < MT * NT; i += 256) {
            int j = i >> 7, rl = i & 127;
            int r = g.m0 + rl, cg = g.n0 + j;
            float v = st[rl * 65 + j] + bias[cg];
            int b = r >> 11, s = r & 2047, hh = cg >> 6, jj = cg & 63;
            long o = ((long)(b * 16 + hh) * 64 + jj) * 2048 + s;
            __half h = __float2half_rn(v);
            outH[o] = h;
            outL[o] = __float2half_rn(v - __half2float(h));
        }
    }
}

// ---------------------------------------------------------------------------
// Output projection: ctx(bf16 hi/lo) @ Wo^T + bo -> fp32
// ---------------------------------------------------------------------------
__global__ void __launch_bounds__(256)
mma_outproj(const __nv_bfloat16* __restrict__ Ah, const __nv_bfloat16* __restrict__ Al,
            const __nv_bfloat16* __restrict__ Bh, const __nv_bfloat16* __restrict__ Bl,
            const float* __restrict__ bias, float* __restrict__ outF)
{
    extern __shared__ uint8_t dsm[];
    GemmCtx g;
    g.sb = smem_u32(dsm);
    g.tid = threadIdx.x; g.lane = g.tid & 31;
    int wid = g.tid >> 5; g.wm = wid >> 1; g.wn = wid & 1;
    g.lrow = g.lane & 15; g.lkh = g.lane >> 4;
    g.n0 = blockIdx.x * NT; g.m0 = blockIdx.y * MT;

    float acc[2][4][4];
    gemm_mainloop(g, dsm, Ah, Al, Bh, Bl, DMODEL, DMODEL, DMODEL, acc);
    stage_acc(dsm, g, acc);

    const float* st = (const float*)dsm;
    for (int i = g.tid; i < MT * NT; i += 256) {
        int row = i >> 6, c = i & 63;
        outF[(long)(g.m0 + row) * 1024 + g.n0 + c] = st[row * 65 + c] + bias[g.n0 + c];
    }
}

// ---------------------------------------------------------------------------
// Fused scores + softmax + context — fp16 (unchanged from R15).
// Pass A: 128 keys/step, 1-pass S, one reduction per step.
// Pass B: 2-pass S, normalize, store attn once, O += P @ (Vh + Vl).
// ---------------------------------------------------------------------------
#define FB_QH   0
#define FB_QL   16384
#define FB_ST0  32768
#define FB_STRIDE 32768
#define FB_PART 98304           // float[2][128]
#define FB_ROWL 99328           // float[128]
#define FB_SM   99840

__global__ void __launch_bounds__(256)
fused_attn_k(const __half* __restrict__ qh, const __half* __restrict__ ql,
             const __half* __restrict__ kh,
             const __half* __restrict__ vth, const __half* __restrict__ vtl,
             float* __restrict__ attn,
             __nv_bfloat16* __restrict__ ch, __nv_bfloat16* __restrict__ cl)
{
    extern __shared__ uint8_t dsm[];
    const uint32_t sb = smem_u32(dsm);
    const int tid = threadIdx.x, wid = tid >> 5, lane = tid & 31;
    const int wm = wid >> 1, wn = wid & 1;
    const int lrow = lane & 15, lkh = lane >> 4;
    const int lr = lane >> 2, lc = lane & 3;
    const int m0 = blockIdx.x * 128;
    const int z = blockIdx.y;
    const long base = (long)(z >> 4) * 2048L * 1024 + (long)(z & 15) * 64;
    const __half* qh_h = qh + base;
    const __half* ql_h = ql + base;
    const __half* kh_h = kh + base;
    const __half* vh_h = vth + (long)z * 64L * 2048;
    const __half* vl_h = vtl + (long)z * 64L * 2048;

    float* part  = (float*)(dsm + FB_PART);
    float* row_l = (float*)(dsm + FB_ROWL);

    auto stage_k128 = [&](int t, int buf) {
        const uint32_t sd = sb + FB_ST0 + buf * FB_STRIDE;
#pragma unroll
        for (int i = 0; i < 4; i++) {
            int chunk = tid + i * 256;
            int row = chunk >> 3, c16 = chunk & 7;
            long g = (long)(t * 128 + row) * 1024 + c16 * 8;
            uint32_t so = SWZ((uint32_t)(row * 128 + c16 * 16));
            cp16(sd + so, kh_h + g);
        }
    };
    auto stage_kv = [&](int t, int buf) {
        const uint32_t sd = sb + FB_ST0 + buf * FB_STRIDE;
#pragma unroll
        for (int i = 0; i < 2; i++) {
            int chunk = tid + i * 256;
            int row = chunk >> 3, c16 = chunk & 7;
            long g = (long)(t * 64 + row) * 1024 + c16 * 8;
            uint32_t so = SWZ((uint32_t)(row * 128 + c16 * 16));
            cp16(sd + so, kh_h + g);
        }
#pragma unroll
        for (int i = 0; i < 2; i++) {
            int chunk = tid + i * 256;               // row = dk 0..63
            int row = chunk >> 3, c16 = chunk & 7;
            long g = (long)row * 2048 + t * 64 + c16 * 8;
            uint32_t so = SWZ((uint32_t)(row * 128 + c16 * 16));
            cp16(sd + 8192 + so, vh_h + g);
            cp16(sd + 16384 + so, vl_h + g);
        }
    };

    auto compute_tile_hi = [&](uint32_t kbase, float acc[2][4][4]) {
#pragma unroll
        for (int i = 0; i < 2; i++)
#pragma unroll
            for (int j = 0; j < 4; j++)
#pragma unroll
                for (int r = 0; r < 4; r++) acc[i][j][r] = 0.0f;
#pragma unroll
        for (int ks = 0; ks < 4; ks++) {
            const uint32_t kb = ks * 32 + lkh * 16;
            uint32_t ah[2][4];
#pragma unroll
            for (int ms = 0; ms < 2; ms++) {
                uint32_t ro = (uint32_t)(wm * 32 + ms * 16 + lrow) * 128 + kb;
                ldsm_x4(ah[ms][0], ah[ms][1], ah[ms][2], ah[ms][3], sb + FB_QH + SWZ(ro));
            }
            uint32_t bh[4][2];
#pragma unroll
            for (int half = 0; half < 2; half++) {
                uint32_t ro = (uint32_t)(wn * 32 + half * 16 + lrow) * 128 + kb;
                uint32_t r0, r1, r2, r3;
                ldsm_x4(r0, r1, r2, r3, kbase + SWZ(ro));
                bh[half * 2 + 0][0] = r0; bh[half * 2 + 0][1] = r2;
                bh[half * 2 + 1][0] = r1; bh[half * 2 + 1][1] = r3;
            }
#pragma unroll
            for (int ms = 0; ms < 2; ms++)
#pragma unroll
                for (int nb = 0; nb < 4; nb++)
                    mma_f16(acc[ms][nb], ah[ms], bh[nb][0], bh[nb][1]);
        }
    };
    auto compute_tile = [&](int buf, float acc[2][4][4]) {
#pragma unroll
        for (int i = 0; i < 2; i++)
#pragma unroll
            for (int j = 0; j < 4; j++)
#pragma unroll
                for (int r = 0; r < 4; r++) acc[i][j][r] = 0.0f;
        const uint32_t kbh = sb + FB_ST0 + buf * FB_STRIDE;
#pragma unroll
        for (int ks = 0; ks < 4; ks++) {
            const uint32_t kb = ks * 32 + lkh * 16;
            uint32_t ah[2][4], al[2][4];
#pragma unroll
            for (int ms = 0; ms < 2; ms++) {
                uint32_t ro = (uint32_t)(wm * 32 + ms * 16 + lrow) * 128 + kb;
                ldsm_x4(ah[ms][0], ah[ms][1], ah[ms][2], ah[ms][3], sb + FB_QH + SWZ(ro));
                ldsm_x4(al[ms][0], al[ms][1], al[ms][2], al[ms][3], sb + FB_QL + SWZ(ro));
            }
            uint32_t bh[4][2];
#pragma unroll
            for (int half = 0; half < 2; half++) {
                uint32_t ro = (uint32_t)(wn * 32 + half * 16 + lrow) * 128 + kb;
                uint32_t r0, r1, r2, r3;
                ldsm_x4(r0, r1, r2, r3, kbh + SWZ(ro));
                bh[half * 2 + 0][0] = r0; bh[half * 2 + 0][1] = r2;
                bh[half * 2 + 1][0] = r1; bh[half * 2 + 1][1] = r3;
            }
#pragma unroll
            for (int ms = 0; ms < 2; ms++)
#pragma unroll
                for (int nb = 0; nb < 4; nb++) {
                    mma_f16(acc[ms][nb], ah[ms], bh[nb][0], bh[nb][1]);
                    mma_f16(acc[ms][nb], al[ms], bh[nb][0], bh[nb][1]);
                }
        }
    };

    // ---- prologue: q tile + first 128-key K block ----
#pragma unroll
    for (int i = 0; i < 4; i++) {
        int chunk = tid + i * 256;
        int row = chunk >> 3, c16 = chunk & 7;
        long g = (long)(m0 + row) * 1024 + c16 * 8;
        uint32_t so = SWZ((uint32_t)(row * 128 + c16 * 16));
        cp16(sb + FB_QH + so, qh_h + g);
        cp16(sb + FB_QL + so, ql_h + g);
    }
    if (tid < 128) row_l[tid] = 0.0f;
    stage_k128(0, 0);
    CP_COMMIT();

    float acc[2][4][4];

    // ---- pass A: 16 steps x 128 keys; one reduction per step ----
    for (int t = 0; t < 16; t++) {
        if (t + 1 < 16) { stage_k128(t + 1, (t + 1) & 1); CP_COMMIT(); CP_WAIT1(); }
        else { CP_WAIT0(); }
        __syncthreads();
        const uint32_t kb0 = sb + FB_ST0 + (t & 1) * FB_STRIDE;
        float s0a[2] = {0.0f, 0.0f}, s1a[2] = {0.0f, 0.0f};
#pragma unroll
        for (int sub = 0; sub < 2; sub++) {
            compute_tile_hi(kb0 + sub * 8192, acc);
#pragma unroll
            for (int ms = 0; ms < 2; ms++) {
#pragma unroll
                for (int nb = 0; nb < 4; nb++) {
                    s0a[ms] += __expf(acc[ms][nb][0] * 0.125f) + __expf(acc[ms][nb][1] * 0.125f);
                    s1a[ms] += __expf(acc[ms][nb][2] * 0.125f) + __expf(acc[ms][nb][3] * 0.125f);
                }
            }
        }
#pragma unroll
        for (int ms = 0; ms < 2; ms++) {
            float s0 = s0a[ms], s1 = s1a[ms];
            s0 += __shfl_xor_sync(0xffffffffu, s0, 1);
            s0 += __shfl_xor_sync(0xffffffffu, s0, 2);
            s1 += __shfl_xor_sync(0xffffffffu, s1, 1);
            s1 += __shfl_xor_sync(0xffffffffu, s1, 2);
            if (lc == 0) {
                part[wn * 128 + wm * 32 + ms * 16 + lr]     = s0;
                part[wn * 128 + wm * 32 + ms * 16 + 8 + lr] = s1;
            }
        }
        __syncthreads();
        if (tid < 128) row_l[tid] += part[tid] + part[128 + tid];
    }
    __syncthreads();
    float inv[2][2];
#pragma unroll
    for (int ms = 0; ms < 2; ms++) {
        inv[ms][0] = 1.0f / row_l[wm * 32 + ms * 16 + lr];
        inv[ms][1] = 1.0f / row_l[wm * 32 + ms * 16 + 8 + lr];
    }

    float accO[2][8][4];
#pragma unroll
    for (int ms = 0; ms < 2; ms++)
#pragma unroll
        for (int dn = 0; dn < 8; dn++)
#pragma unroll
            for (int r = 0; r < 4; r++) accO[ms][dn][r] = 0.0f;

    // ---- pass B: 2-pass S, normalize, store attn, O += P @ (Vh + Vl) ----
    stage_kv(0, 0);
    CP_COMMIT();
    for (int t = 0; t < 32; t++) {
        if (t + 1 < 32) { stage_kv(t + 1, (t + 1) & 1); CP_COMMIT(); CP_WAIT1(); }
        else { CP_WAIT0(); }
        __syncthreads();
        compute_tile(t & 1, acc);

#pragma unroll
        for (int ms = 0; ms < 2; ms++)
#pragma unroll
            for (int nb = 0; nb < 4; nb++) {
                acc[ms][nb][0] = __expf(acc[ms][nb][0] * 0.125f) * inv[ms][0];
                acc[ms][nb][1] = __expf(acc[ms][nb][1] * 0.125f) * inv[ms][0];
                acc[ms][nb][2] = __expf(acc[ms][nb][2] * 0.125f) * inv[ms][1];
                acc[ms][nb][3] = __expf(acc[ms][nb][3] * 0.125f) * inv[ms][1];
            }

        const int colb = t * 64 + wn * 32 + lc * 2;
#pragma unroll
        for (int ms = 0; ms < 2; ms++) {
            long rb0 = ((long)z * 2048 + m0 + wm * 32 + ms * 16 + lr) * 2048;
            long rb1 = rb0 + 8L * 2048;
#pragma unroll
            for (int nb = 0; nb < 4; nb++) {
                *(float2*)(attn + rb0 + colb + nb * 8) =
                    make_float2(acc[ms][nb][0], acc[ms][nb][1]);
                *(float2*)(attn + rb1 + colb + nb * 8) =
                    make_float2(acc[ms][nb][2], acc[ms][nb][3]);
            }
        }

        // O += P @ (Vh + Vl)
        const uint32_t vbh = sb + FB_ST0 + (t & 1) * FB_STRIDE + 8192;
        const uint32_t vbl = vbh + 8192;
#pragma unroll
        for (int kh2 = 0; kh2 < 2; kh2++) {
            uint32_t vh[8][2], vl[8][2];
#pragma unroll
            for (int dh = 0; dh < 4; dh++) {
                uint32_t ro = (uint32_t)(dh * 16 + lrow) * 128 +
                              (uint32_t)(wn * 32 + kh2 * 16) * 2 + lkh * 16;
                uint32_t r0, r1, r2, r3;
                ldsm_x4(r0, r1, r2, r3, vbh + SWZ(ro));
                vh[dh * 2 + 0][0] = r0; vh[dh * 2 + 0][1] = r2;
                vh[dh * 2 + 1][0] = r1; vh[dh * 2 + 1][1] = r3;
                ldsm_x4(r0, r1, r2, r3, vbl + SWZ(ro));
                vl[dh * 2 + 0][0] = r0; vl[dh * 2 + 0][1] = r2;
                vl[dh * 2 + 1][0] = r1; vl[dh * 2 + 1][1] = r3;
            }
#pragma unroll
            for (int ms = 0; ms < 2; ms++) {
                const float* c0 = acc[ms][2 * kh2];
                const float* c1 = acc[ms][2 * kh2 + 1];
                uint32_t ph[4];
                ph[0] = pack_half(c0[0], c0[1]);
                ph[1] = pack_half(c0[2], c0[3]);
                ph[2] = pack_half(c1[0], c1[1]);
                ph[3] = pack_half(c1[2], c1[3]);
#pragma unroll
                for (int dn = 0; dn < 8; dn++) {
                    mma_f16(accO[ms][dn], ph, vh[dn][0], vh[dn][1]);
                    mma_f16(accO[ms][dn], ph, vl[dn][0], vl[dn][1]);
                }
            }
        }
        __syncthreads();
    }

    // ---- ctx epilogue: cross-wn reduce in smem, bf16 split store [B,S,D] ----
    float* st = (float*)dsm;
    {
        const int lc2 = lc * 2;
        if (wn == 0) {
#pragma unroll
            for (int ms = 0; ms < 2; ms++)
#pragma unroll
                for (int dn = 0; dn < 8; dn++) {
                    int r = wm * 32 + ms * 16 + lr;
                    int c = dn * 8 + lc2;
                    st[r * 65 + c]           = accO[ms][dn][0];
                    st[r * 65 + c + 1]       = accO[ms][dn][1];
                    st[(r + 8) * 65 + c]     = accO[ms][dn][2];
                    st[(r + 8) * 65 + c + 1] = accO[ms][dn][3];
                }
        }
        __syncthreads();
        if (wn == 1) {
#pragma unroll
            for (int ms = 0; ms < 2; ms++)
#pragma unroll
                for (int dn = 0; dn < 8; dn++) {
                    int r = wm * 32 + ms * 16 + lr;
                    int c = dn * 8 + lc2;
                    st[r * 65 + c]           += accO[ms][dn][0];
                    st[r * 65 + c + 1]       += accO[ms][dn][1];
                    st[(r + 8) * 65 + c]     += accO[ms][dn][2];
                    st[(r + 8) * 65 + c + 1] += accO[ms][dn][3];
                }
        }
        __syncthreads();
    }
    {
        const int b = z >> 4, hh = z & 15;
        for (int i = tid; i < 128 * 64; i += 256) {
            int row = i >> 6, c = i & 63;
            float v = st[row * 65 + c];
            long o = (long)((b << 11) + m0 + row) * 1024 + hh * 64 + c;
            __nv_bfloat16 h = __float2bfloat16(v);
            ch[o] = h;
            cl[o] = __float2bfloat16(v - __bfloat162float(h));
        }
    }
}

// ---------------------------------------------------------------------------
extern "C" void kernel_launch(void* const* d_in, const int* in_sizes, int n_in,
                              void* d_out, int out_size)
{
    const float* Q  = (const float*)d_in[0];
    const float* K  = (const float*)d_in[1];
    const float* V  = (const float*)d_in[2];
    const float* Wq = (const float*)d_in[3];
    const float* bq = (const float*)d_in[4];
    const float* Wk = (const float*)d_in[5];
    const float* bk = (const float*)d_in[6];
    const float* Wv = (const float*)d_in[7];
    const float* bv = (const float*)d_in[8];
    const float* Wo = (const float*)d_in[9];
    const float* bo = (const float*)d_in[10];
    float* out = (float*)d_out;

    __nv_bfloat16 *Qh, *Ql, *Kh, *Kl, *Vh, *Vl;
    __nv_bfloat16 *Wqh, *Wql, *Wkh, *Wkl, *Wvh, *Wvl, *Woh, *Wol;
    __half *qh, *ql, *kh, *vth, *vtl;
    __nv_bfloat16 *ch, *cl;
    float* attn_scratch;
    cudaGetSymbolAddress((void**)&Qh, g_Qh);   cudaGetSymbolAddress((void**)&Ql, g_Ql);
    cudaGetSymbolAddress((void**)&Kh, g_Kh);   cudaGetSymbolAddress((void**)&Kl, g_Kl);
    cudaGetSymbolAddress((void**)&Vh, g_Vh);   cudaGetSymbolAddress((void**)&Vl, g_Vl);
    cudaGetSymbolAddress((void**)&Wqh, g_Wqh); cudaGetSymbolAddress((void**)&Wql, g_Wql);
    cudaGetSymbolAddress((void**)&Wkh, g_Wkh); cudaGetSymbolAddress((void**)&Wkl, g_Wkl);
    cudaGetSymbolAddress((void**)&Wvh, g_Wvh); cudaGetSymbolAddress((void**)&Wvl, g_Wvl);
    cudaGetSymbolAddress((void**)&Woh, g_Woh); cudaGetSymbolAddress((void**)&Wol, g_Wol);
    cudaGetSymbolAddress((void**)&qh, g_qh);   cudaGetSymbolAddress((void**)&ql, g_ql);
    cudaGetSymbolAddress((void**)&kh, g_kh);
    cudaGetSymbolAddress((void**)&vth, g_vth); cudaGetSymbolAddress((void**)&vtl, g_vtl);
    cudaGetSymbolAddress((void**)&ch, g_ch);   cudaGetSymbolAddress((void**)&cl, g_cl);
    cudaGetSymbolAddress((void**)&attn_scratch, g_attn);

    float* attn = ((long)out_size >= OUT_TOTAL) ? (out + OUT0) : attn_scratch;

    cudaFuncSetAttribute(mma_proj3,   cudaFuncAttributeMaxDynamicSharedMemorySize, SM_PIPE);
    cudaFuncSetAttribute(mma_outproj, cudaFuncAttributeMaxDynamicSharedMemorySize, SM_PIPE);
    cudaFuncSetAttribute(fused_attn_k, cudaFuncAttributeMaxDynamicSharedMemorySize, FB_SM);

    // 0) One-launch split of all 7 fp32 inputs into bf16 hi/lo
    {
        SplitArgs a;
        a.x[0] = Q;  a.h[0] = Qh;  a.l[0] = Ql;  a.n4[0] = TOKENS * DMODEL / 4;
        a.x[1] = K;  a.h[1] = Kh;  a.l[1] = Kl;  a.n4[1] = TOKENS * DMODEL / 4;
        a.x[2] = V;  a.h[2] = Vh;  a.l[2] = Vl;  a.n4[2] = TOKENS * DMODEL / 4;
        a.x[3] = Wq; a.h[3] = Wqh; a.l[3] = Wql; a.n4[3] = DMODEL * DMODEL / 4;
        a.x[4] = Wk; a.h[4] = Wkh; a.l[4] = Wkl; a.n4[4] = DMODEL * DMODEL / 4;
        a.x[5] = Wv; a.h[5] = Wvh; a.l[5] = Wvl; a.n4[5] = DMODEL * DMODEL / 4;
        a.x[6] = Wo; a.h[6] = Woh; a.l[6] = Wol; a.n4[6] = DMODEL * DMODEL / 4;
        dim3 gs((TOKENS * DMODEL / 4 + 255) / 256, 7, 1);
        split_all<<<gs, 256>>>(a);
    }

    // 1) Merged Q/K/V projections in ONE launch (grid.z = 3)
    {
        ProjArgs pa;
        pa.Ah[0] = Qh; pa.Al[0] = Ql; pa.Bh[0] = Wqh; pa.Bl[0] = Wql;
        pa.bias[0] = bq; pa.outH[0] = qh; pa.outL[0] = ql;
        pa.Ah[1] = Kh; pa.Al[1] = Kl; pa.Bh[1] = Wkh; pa.Bl[1] = Wkl;
        pa.bias[1] = bk; pa.outH[1] = kh; pa.outL[1] = nullptr;
        pa.Ah[2] = Vh; pa.Al[2] = Vl; pa.Bh[2] = Wvh; pa.Bl[2] = Wvl;
        pa.bias[2] = bv; pa.outH[2] = vth; pa.outL[2] = vtl;
        dim3 gp(DMODEL / NT, TOKENS / MT, 3);                   // (16, 32, 3)
        mma_proj3<<<gp, 256, SM_PIPE>>>(pa);
    }

    // 2) Fused scores + softmax + context
    dim3 gf(SEQ / 128, BH, 1);                                  // (16, 32)
    fused_attn_k<<<gf, 256, FB_SM>>>(qh, ql, kh, vth, vtl, attn, ch, cl);

    // 3) Output projection: ctx @ Wo^T + bo -> out fp32
    dim3 go(DMODEL / NT, TOKENS / MT, 1);
    mma_outproj<<<go, 256, SM_PIPE>>>(ch, cl, Woh, Wol, bo, out);

    (void)n_in; (void)in_sizes;
}

// round 17
// speedup vs baseline: 1.2690x; 1.0544x over previous
#include <cuda_runtime.h>
#include <cuda_bf16.h>
#include <cuda_fp16.h>
#include <cstdint>

// ---------------------------------------------------------------------------
// Problem constants
// ---------------------------------------------------------------------------
#define BATCH   2
#define SEQ     2048
#define DMODEL  1024
#define NHEAD   16
#define DK      64
#define BH      (BATCH * NHEAD)              // 32
#define TOKENS  (BATCH * SEQ)                // 4096
#define OUT0    (TOKENS * DMODEL)            // 4,194,304
#define ATTN_N  ((long)BH * SEQ * SEQ)       // 134,217,728
#define OUT_TOTAL (OUT0 + ATTN_N)

// ---------------------------------------------------------------------------
// Scratch (static device arrays; no cudaMalloc anywhere)
// ---------------------------------------------------------------------------
__device__ __nv_bfloat16 g_Qh[TOKENS * DMODEL], g_Ql[TOKENS * DMODEL];
__device__ __nv_bfloat16 g_Kh[TOKENS * DMODEL], g_Kl[TOKENS * DMODEL];
__device__ __nv_bfloat16 g_Vh[TOKENS * DMODEL], g_Vl[TOKENS * DMODEL];
__device__ __nv_bfloat16 g_Wqh[DMODEL * DMODEL], g_Wql[DMODEL * DMODEL];
__device__ __nv_bfloat16 g_Wkh[DMODEL * DMODEL], g_Wkl[DMODEL * DMODEL];
__device__ __nv_bfloat16 g_Wvh[DMODEL * DMODEL], g_Wvl[DMODEL * DMODEL];
__device__ __nv_bfloat16 g_Woh[DMODEL * DMODEL], g_Wol[DMODEL * DMODEL];
__device__ __half g_qh[TOKENS * DMODEL];                             // fp16 (hi only)
__device__ __half g_kh[TOKENS * DMODEL];                             // fp16 (hi only)
__device__ __half g_vth[BH * DK * SEQ], g_vtl[BH * DK * SEQ];        // fp16 V^T hi/lo
__device__ __nv_bfloat16 g_ch[TOKENS * DMODEL], g_cl[TOKENS * DMODEL];  // ctx bf16
__device__ float g_attn[ATTN_N];                 // fallback if d_out lacks attn

// ---------------------------------------------------------------------------
// Helpers
// ---------------------------------------------------------------------------
__device__ __forceinline__ uint32_t smem_u32(const void* p) {
    uint32_t a;
    asm("{ .reg .u64 t; cvta.to.shared.u64 t, %1; cvt.u32.u64 %0, t; }"
        : "=r"(a) : "l"(p));
    return a;
}
#define SWZ(off) ((off) ^ (((off) >> 3) & 0x70))

__device__ __forceinline__ void ldsm_x4(uint32_t& r0, uint32_t& r1,
                                        uint32_t& r2, uint32_t& r3, uint32_t a) {
    asm volatile("ldmatrix.sync.aligned.m8n8.x4.shared.b16 {%0,%1,%2,%3}, [%4];"
                 : "=r"(r0), "=r"(r1), "=r"(r2), "=r"(r3) : "r"(a));
}
__device__ __forceinline__ void mma_bf16(float* c, const uint32_t* a,
                                         uint32_t b0, uint32_t b1) {
    asm volatile(
        "mma.sync.aligned.m16n8k16.row.col.f32.bf16.bf16.f32 "
        "{%0,%1,%2,%3}, {%4,%5,%6,%7}, {%8,%9}, {%0,%1,%2,%3};"
        : "+f"(c[0]), "+f"(c[1]), "+f"(c[2]), "+f"(c[3])
        : "r"(a[0]), "r"(a[1]), "r"(a[2]), "r"(a[3]), "r"(b0), "r"(b1));
}
__device__ __forceinline__ void mma_f16(float* c, const uint32_t* a,
                                        uint32_t b0, uint32_t b1) {
    asm volatile(
        "mma.sync.aligned.m16n8k16.row.col.f32.f16.f16.f32 "
        "{%0,%1,%2,%3}, {%4,%5,%6,%7}, {%8,%9}, {%0,%1,%2,%3};"
        : "+f"(c[0]), "+f"(c[1]), "+f"(c[2]), "+f"(c[3])
        : "r"(a[0]), "r"(a[1]), "r"(a[2]), "r"(a[3]), "r"(b0), "r"(b1));
}
__device__ __forceinline__ void cp16(uint32_t dst, const void* src) {
    asm volatile("cp.async.cg.shared.global [%0], [%1], 16;"
                 :: "r"(dst), "l"(src) : "memory");
}
#define CP_COMMIT() asm volatile("cp.async.commit_group;" ::: "memory")
#define CP_WAIT1()  asm volatile("cp.async.wait_group 1;" ::: "memory")
#define CP_WAIT0()  asm volatile("cp.async.wait_group 0;" ::: "memory")

__device__ __forceinline__ uint32_t pack_half(float lo, float hi) {
    uint32_t r;
    asm("cvt.rn.f16x2.f32 %0, %1, %2;" : "=r"(r) : "f"(hi), "f"(lo));
    return r;
}

// ---------------------------------------------------------------------------
// One-launch fp32 -> bf16 hi/lo split over all 7 inputs (grid.y = segment)
// ---------------------------------------------------------------------------
struct SplitArgs {
    const float* x[7];
    __nv_bfloat16* h[7];
    __nv_bfloat16* l[7];
    int n4[7];
};

__global__ void __launch_bounds__(256)
split_all(SplitArgs a)
{
    const int seg = blockIdx.y;
    const int i = blockIdx.x * 256 + threadIdx.x;
    if (i >= a.n4[seg]) return;
    float4 v = ((const float4*)a.x[seg])[i];
    __nv_bfloat16 h0 = __float2bfloat16(v.x), h1 = __float2bfloat16(v.y);
    __nv_bfloat16 h2 = __float2bfloat16(v.z), h3 = __float2bfloat16(v.w);
    float l0 = v.x - __bfloat162float(h0), l1 = v.y - __bfloat162float(h1);
    float l2 = v.z - __bfloat162float(h2), l3 = v.w - __bfloat162float(h3);
    uint2 hv, lv;
    hv.x = (uint32_t)__bfloat16_as_ushort(h0) | ((uint32_t)__bfloat16_as_ushort(h1) << 16);
    hv.y = (uint32_t)__bfloat16_as_ushort(h2) | ((uint32_t)__bfloat16_as_ushort(h3) << 16);
    lv.x = (uint32_t)__bfloat16_as_ushort(__float2bfloat16(l0)) |
           ((uint32_t)__bfloat16_as_ushort(__float2bfloat16(l1)) << 16);
    lv.y = (uint32_t)__bfloat16_as_ushort(__float2bfloat16(l2)) |
           ((uint32_t)__bfloat16_as_ushort(__float2bfloat16(l3)) << 16);
    ((uint2*)a.h[seg])[i] = hv;
    ((uint2*)a.l[seg])[i] = lv;
}

// ---------------------------------------------------------------------------
// GEMM mainloop config (R12/R15 proven optimum): KT=64, 4 planes, 96KB,
// no reg cap, 96 MMAs/sync, M=128 x N=64 tile, 8 warps (4x2), 32x32/warp.
// ---------------------------------------------------------------------------
#define MT 128
#define NT 64
#define KT 64
#define STG_STRIDE 49152
#define OFF_AH 0
#define OFF_AL 16384
#define OFF_BH 32768
#define OFF_BL 40960
#define SM_PIPE  98304

struct GemmCtx {
    uint32_t sb; int tid, lane, wm, wn, lrow, lkh, n0, m0;
};

__device__ __forceinline__ void gemm_mainloop(
    const GemmCtx& g, uint8_t* dsm,
    const __nv_bfloat16* __restrict__ Ah, const __nv_bfloat16* __restrict__ Al,
    const __nv_bfloat16* __restrict__ Bh, const __nv_bfloat16* __restrict__ Bl,
    int K, int lda, int ldb, float acc[2][4][4])
{
#pragma unroll
    for (int i = 0; i < 2; i++)
#pragma unroll
        for (int j = 0; j < 4; j++)
#pragma unroll
            for (int r = 0; r < 4; r++) acc[i][j][r] = 0.0f;

    const int ntiles = K / KT;
    auto stage = [&](int kti, int buf) {
        const uint32_t b0 = g.sb + buf * STG_STRIDE;
        const int kt = kti * KT;
#pragma unroll
        for (int i = 0; i < 4; i++) {
            int chunk = g.tid + i * 256;
            int row = chunk >> 3, c16 = chunk & 7;
            long gg = (long)(g.m0 + row) * lda + kt + c16 * 8;
            uint32_t so = SWZ((uint32_t)(row * 128 + c16 * 16));
            cp16(b0 + OFF_AH + so, Ah + gg);
            cp16(b0 + OFF_AL + so, Al + gg);
        }
#pragma unroll
        for (int i = 0; i < 2; i++) {
            int chunk = g.tid + i * 256;
            int row = chunk >> 3, c16 = chunk & 7;
            long gg = (long)(g.n0 + row) * ldb + kt + c16 * 8;
            uint32_t so = SWZ((uint32_t)(row * 128 + c16 * 16));
            cp16(b0 + OFF_BH + so, Bh + gg);
            cp16(b0 + OFF_BL + so, Bl + gg);
        }
    };
    stage(0, 0);
    CP_COMMIT();
    for (int t = 0; t < ntiles; t++) {
        if (t + 1 < ntiles) { stage(t + 1, (t + 1) & 1); CP_COMMIT(); CP_WAIT1(); }
        else { CP_WAIT0(); }
        __syncthreads();
        const uint32_t b0 = g.sb + (t & 1) * STG_STRIDE;
#pragma unroll
        for (int ks = 0; ks < 4; ks++) {
            const uint32_t kb = ks * 32 + g.lkh * 16;
            uint32_t ah[2][4], al[2][4];
#pragma unroll
            for (int ms = 0; ms < 2; ms++) {
                uint32_t ro = (uint32_t)(g.wm * 32 + ms * 16 + g.lrow) * 128 + kb;
                ldsm_x4(ah[ms][0], ah[ms][1], ah[ms][2], ah[ms][3], b0 + OFF_AH + SWZ(ro));
                ldsm_x4(al[ms][0], al[ms][1], al[ms][2], al[ms][3], b0 + OFF_AL + SWZ(ro));
            }
            uint32_t bh[4][2], bl[4][2];
#pragma unroll
            for (int half = 0; half < 2; half++) {
                uint32_t ro = (uint32_t)(g.wn * 32 + half * 16 + g.lrow) * 128 + kb;
                uint32_t r0, r1, r2, r3;
                ldsm_x4(r0, r1, r2, r3, b0 + OFF_BH + SWZ(ro));
                bh[half * 2 + 0][0] = r0; bh[half * 2 + 0][1] = r2;
                bh[half * 2 + 1][0] = r1; bh[half * 2 + 1][1] = r3;
                ldsm_x4(r0, r1, r2, r3, b0 + OFF_BL + SWZ(ro));
                bl[half * 2 + 0][0] = r0; bl[half * 2 + 0][1] = r2;
                bl[half * 2 + 1][0] = r1; bl[half * 2 + 1][1] = r3;
            }
#pragma unroll
            for (int ms = 0; ms < 2; ms++)
#pragma unroll
                for (int nb = 0; nb < 4; nb++) {
                    mma_bf16(acc[ms][nb], ah[ms], bh[nb][0], bh[nb][1]);
                    mma_bf16(acc[ms][nb], al[ms], bh[nb][0], bh[nb][1]);
                    mma_bf16(acc[ms][nb], ah[ms], bl[nb][0], bl[nb][1]);
                }
        }
        __syncthreads();
    }
}

__device__ __forceinline__ void stage_acc(uint8_t* dsm, const GemmCtx& g,
                                          float acc[2][4][4])
{
    float* st = (float*)dsm;                     // [128][65]
    const int lr = g.lane >> 2, lc = (g.lane & 3) * 2;
#pragma unroll
    for (int ms = 0; ms < 2; ms++)
#pragma unroll
        for (int nb = 0; nb < 4; nb++) {
            int r = g.wm * 32 + ms * 16 + lr;
            int c = g.wn * 32 + nb * 8 + lc;
            st[r * 65 + c]            = acc[ms][nb][0];
            st[r * 65 + c + 1]        = acc[ms][nb][1];
            st[(r + 8) * 65 + c]      = acc[ms][nb][2];
            st[(r + 8) * 65 + c + 1]  = acc[ms][nb][3];
        }
    __syncthreads();
}

// ---------------------------------------------------------------------------
// Merged Q/K/V projection kernel: grid.z selects the projection.
// z=0: Q -> fp16 hi only;  z=1: K -> fp16 hi only;
// z=2: V -> fp16 hi/lo transposed per-head [BH,64,S].
// ---------------------------------------------------------------------------
struct ProjArgs {
    const __nv_bfloat16 *Ah[3], *Al[3], *Bh[3], *Bl[3];
    const float* bias[3];
    __half *outH[3], *outL[3];
};

__global__ void __launch_bounds__(256)
mma_proj3(ProjArgs pa)
{
    extern __shared__ uint8_t dsm[];
    const int z = blockIdx.z;
    GemmCtx g;
    g.sb = smem_u32(dsm);
    g.tid = threadIdx.x; g.lane = g.tid & 31;
    int wid = g.tid >> 5; g.wm = wid >> 1; g.wn = wid & 1;
    g.lrow = g.lane & 15; g.lkh = g.lane >> 4;
    g.n0 = blockIdx.x * NT; g.m0 = blockIdx.y * MT;

    float acc[2][4][4];
    gemm_mainloop(g, dsm, pa.Ah[z], pa.Al[z], pa.Bh[z], pa.Bl[z],
                  DMODEL, DMODEL, DMODEL, acc);
    stage_acc(dsm, g, acc);

    const float* st = (const float*)dsm;
    const float* bias = pa.bias[z];
    __half* outH = pa.outH[z];
    __half* outL = pa.outL[z];

    if (z < 2) {             // Q or K: bias + fp16 hi only, ld 1024
        for (int i = g.tid; i < MT * NT; i += 256) {
            int row = i >> 6, c = i & 63;
            float v = st[row * 65 + c] + bias[g.n0 + c];
            outH[(long)(g.m0 + row) * 1024 + g.n0 + c] = __float2half_rn(v);
        }
    } else {                 // V: bias + fp16 hi/lo, transposed [BH,64,S]
        for (int i = g.tid; i < MT * NT; i += 256) {
            int j = i >> 7, rl = i & 127;
            int r = g.m0 + rl, cg = g.n0 + j;
            float v = st[rl * 65 + j] + bias[cg];
            int b = r >> 11, s = r & 2047, hh = cg >> 6, jj = cg & 63;
            long o = ((long)(b * 16 + hh) * 64 + jj) * 2048 + s;
            __half h = __float2half_rn(v);
            outH[o] = h;
            outL[o] = __float2half_rn(v - __half2float(h));
        }
    }
}

// ---------------------------------------------------------------------------
// Output projection: ctx(bf16 hi/lo) @ Wo^T + bo -> fp32
// ---------------------------------------------------------------------------
__global__ void __launch_bounds__(256)
mma_outproj(const __nv_bfloat16* __restrict__ Ah, const __nv_bfloat16* __restrict__ Al,
            const __nv_bfloat16* __restrict__ Bh, const __nv_bfloat16* __restrict__ Bl,
            const float* __restrict__ bias, float* __restrict__ outF)
{
    extern __shared__ uint8_t dsm[];
    GemmCtx g;
    g.sb = smem_u32(dsm);
    g.tid = threadIdx.x; g.lane = g.tid & 31;
    int wid = g.tid >> 5; g.wm = wid >> 1; g.wn = wid & 1;
    g.lrow = g.lane & 15; g.lkh = g.lane >> 4;
    g.n0 = blockIdx.x * NT; g.m0 = blockIdx.y * MT;

    float acc[2][4][4];
    gemm_mainloop(g, dsm, Ah, Al, Bh, Bl, DMODEL, DMODEL, DMODEL, acc);
    stage_acc(dsm, g, acc);

    const float* st = (const float*)dsm;
    for (int i = g.tid; i < MT * NT; i += 256) {
        int row = i >> 6, c = i & 63;
        outF[(long)(g.m0 + row) * 1024 + g.n0 + c] = st[row * 65 + c] + bias[g.n0 + c];
    }
}

// ---------------------------------------------------------------------------
// Fused scores + softmax + context — fp16, 1-pass S everywhere.
// Pass A: 128 keys/step, S = qh*kh, one reduction per step.
// Pass B: S = qh*kh (identical arithmetic to pass A), normalize,
//         store attn once, O += P @ (Vh + Vl), cross-wn reduce, bf16 ctx.
// Q occupies FB_QH only (ql eliminated).
// ---------------------------------------------------------------------------
#define FB_QH   0
#define FB_ST0  32768
#define FB_STRIDE 32768
#define FB_PART 98304           // float[2][128]
#define FB_ROWL 99328           // float[128]
#define FB_SM   99840

__global__ void __launch_bounds__(256)
fused_attn_k(const __half* __restrict__ qh,
             const __half* __restrict__ kh,
             const __half* __restrict__ vth, const __half* __restrict__ vtl,
             float* __restrict__ attn,
             __nv_bfloat16* __restrict__ ch, __nv_bfloat16* __restrict__ cl)
{
    extern __shared__ uint8_t dsm[];
    const uint32_t sb = smem_u32(dsm);
    const int tid = threadIdx.x, wid = tid >> 5, lane = tid & 31;
    const int wm = wid >> 1, wn = wid & 1;
    const int lrow = lane & 15, lkh = lane >> 4;
    const int lr = lane >> 2, lc = lane & 3;
    const int m0 = blockIdx.x * 128;
    const int z = blockIdx.y;
    const long base = (long)(z >> 4) * 2048L * 1024 + (long)(z & 15) * 64;
    const __half* qh_h = qh + base;
    const __half* kh_h = kh + base;
    const __half* vh_h = vth + (long)z * 64L * 2048;
    const __half* vl_h = vtl + (long)z * 64L * 2048;

    float* part  = (float*)(dsm + FB_PART);
    float* row_l = (float*)(dsm + FB_ROWL);

    auto stage_k128 = [&](int t, int buf) {
        const uint32_t sd = sb + FB_ST0 + buf * FB_STRIDE;
#pragma unroll
        for (int i = 0; i < 4; i++) {
            int chunk = tid + i * 256;
            int row = chunk >> 3, c16 = chunk & 7;
            long g = (long)(t * 128 + row) * 1024 + c16 * 8;
            uint32_t so = SWZ((uint32_t)(row * 128 + c16 * 16));
            cp16(sd + so, kh_h + g);
        }
    };
    auto stage_kv = [&](int t, int buf) {
        const uint32_t sd = sb + FB_ST0 + buf * FB_STRIDE;
#pragma unroll
        for (int i = 0; i < 2; i++) {
            int chunk = tid + i * 256;
            int row = chunk >> 3, c16 = chunk & 7;
            long g = (long)(t * 64 + row) * 1024 + c16 * 8;
            uint32_t so = SWZ((uint32_t)(row * 128 + c16 * 16));
            cp16(sd + so, kh_h + g);
        }
#pragma unroll
        for (int i = 0; i < 2; i++) {
            int chunk = tid + i * 256;               // row = dk 0..63
            int row = chunk >> 3, c16 = chunk & 7;
            long g = (long)row * 2048 + t * 64 + c16 * 8;
            uint32_t so = SWZ((uint32_t)(row * 128 + c16 * 16));
            cp16(sd + 8192 + so, vh_h + g);
            cp16(sd + 16384 + so, vl_h + g);
        }
    };

    // 1-pass S tile from explicit smem K base
    auto compute_s = [&](uint32_t kbase, float acc[2][4][4]) {
#pragma unroll
        for (int i = 0; i < 2; i++)
#pragma unroll
            for (int j = 0; j < 4; j++)
#pragma unroll
                for (int r = 0; r < 4; r++) acc[i][j][r] = 0.0f;
#pragma unroll
        for (int ks = 0; ks < 4; ks++) {
            const uint32_t kb = ks * 32 + lkh * 16;
            uint32_t ah[2][4];
#pragma unroll
            for (int ms = 0; ms < 2; ms++) {
                uint32_t ro = (uint32_t)(wm * 32 + ms * 16 + lrow) * 128 + kb;
                ldsm_x4(ah[ms][0], ah[ms][1], ah[ms][2], ah[ms][3], sb + FB_QH + SWZ(ro));
            }
            uint32_t bh[4][2];
#pragma unroll
            for (int half = 0; half < 2; half++) {
                uint32_t ro = (uint32_t)(wn * 32 + half * 16 + lrow) * 128 + kb;
                uint32_t r0, r1, r2, r3;
                ldsm_x4(r0, r1, r2, r3, kbase + SWZ(ro));
                bh[half * 2 + 0][0] = r0; bh[half * 2 + 0][1] = r2;
                bh[half * 2 + 1][0] = r1; bh[half * 2 + 1][1] = r3;
            }
#pragma unroll
            for (int ms = 0; ms < 2; ms++)
#pragma unroll
                for (int nb = 0; nb < 4; nb++)
                    mma_f16(acc[ms][nb], ah[ms], bh[nb][0], bh[nb][1]);
        }
    };

    // ---- prologue: q tile (hi only) + first 128-key K block ----
#pragma unroll
    for (int i = 0; i < 4; i++) {
        int chunk = tid + i * 256;
        int row = chunk >> 3, c16 = chunk & 7;
        long g = (long)(m0 + row) * 1024 + c16 * 8;
        uint32_t so = SWZ((uint32_t)(row * 128 + c16 * 16));
        cp16(sb + FB_QH + so, qh_h + g);
    }
    if (tid < 128) row_l[tid] = 0.0f;
    stage_k128(0, 0);
    CP_COMMIT();

    float acc[2][4][4];

    // ---- pass A: 16 steps x 128 keys; one reduction per step ----
    for (int t = 0; t < 16; t++) {
        if (t + 1 < 16) { stage_k128(t + 1, (t + 1) & 1); CP_COMMIT(); CP_WAIT1(); }
        else { CP_WAIT0(); }
        __syncthreads();
        const uint32_t kb0 = sb + FB_ST0 + (t & 1) * FB_STRIDE;
        float s0a[2] = {0.0f, 0.0f}, s1a[2] = {0.0f, 0.0f};
#pragma unroll
        for (int sub = 0; sub < 2; sub++) {
            compute_s(kb0 + sub * 8192, acc);
#pragma unroll
            for (int ms = 0; ms < 2; ms++) {
#pragma unroll
                for (int nb = 0; nb < 4; nb++) {
                    s0a[ms] += __expf(acc[ms][nb][0] * 0.125f) + __expf(acc[ms][nb][1] * 0.125f);
                    s1a[ms] += __expf(acc[ms][nb][2] * 0.125f) + __expf(acc[ms][nb][3] * 0.125f);
                }
            }
        }
#pragma unroll
        for (int ms = 0; ms < 2; ms++) {
            float s0 = s0a[ms], s1 = s1a[ms];
            s0 += __shfl_xor_sync(0xffffffffu, s0, 1);
            s0 += __shfl_xor_sync(0xffffffffu, s0, 2);
            s1 += __shfl_xor_sync(0xffffffffu, s1, 1);
            s1 += __shfl_xor_sync(0xffffffffu, s1, 2);
            if (lc == 0) {
                part[wn * 128 + wm * 32 + ms * 16 + lr]     = s0;
                part[wn * 128 + wm * 32 + ms * 16 + 8 + lr] = s1;
            }
        }
        __syncthreads();
        if (tid < 128) row_l[tid] += part[tid] + part[128 + tid];
    }
    __syncthreads();
    float inv[2][2];
#pragma unroll
    for (int ms = 0; ms < 2; ms++) {
        inv[ms][0] = 1.0f / row_l[wm * 32 + ms * 16 + lr];
        inv[ms][1] = 1.0f / row_l[wm * 32 + ms * 16 + 8 + lr];
    }

    float accO[2][8][4];
#pragma unroll
    for (int ms = 0; ms < 2; ms++)
#pragma unroll
        for (int dn = 0; dn < 8; dn++)
#pragma unroll
            for (int r = 0; r < 4; r++) accO[ms][dn][r] = 0.0f;

    // ---- pass B: 1-pass S, normalize, store attn, O += P @ (Vh + Vl) ----
    stage_kv(0, 0);
    CP_COMMIT();
    for (int t = 0; t < 32; t++) {
        if (t + 1 < 32) { stage_kv(t + 1, (t + 1) & 1); CP_COMMIT(); CP_WAIT1(); }
        else { CP_WAIT0(); }
        __syncthreads();
        compute_s(sb + FB_ST0 + (t & 1) * FB_STRIDE, acc);

#pragma unroll
        for (int ms = 0; ms < 2; ms++)
#pragma unroll
            for (int nb = 0; nb < 4; nb++) {
                acc[ms][nb][0] = __expf(acc[ms][nb][0] * 0.125f) * inv[ms][0];
                acc[ms][nb][1] = __expf(acc[ms][nb][1] * 0.125f) * inv[ms][0];
                acc[ms][nb][2] = __expf(acc[ms][nb][2] * 0.125f) * inv[ms][1];
                acc[ms][nb][3] = __expf(acc[ms][nb][3] * 0.125f) * inv[ms][1];
            }

        const int colb = t * 64 + wn * 32 + lc * 2;
#pragma unroll
        for (int ms = 0; ms < 2; ms++) {
            long rb0 = ((long)z * 2048 + m0 + wm * 32 + ms * 16 + lr) * 2048;
            long rb1 = rb0 + 8L * 2048;
#pragma unroll
            for (int nb = 0; nb < 4; nb++) {
                *(float2*)(attn + rb0 + colb + nb * 8) =
                    make_float2(acc[ms][nb][0], acc[ms][nb][1]);
                *(float2*)(attn + rb1 + colb + nb * 8) =
                    make_float2(acc[ms][nb][2], acc[ms][nb][3]);
            }
        }

        // O += P @ (Vh + Vl)
        const uint32_t vbh = sb + FB_ST0 + (t & 1) * FB_STRIDE + 8192;
        const uint32_t vbl = vbh + 8192;
#pragma unroll
        for (int kh2 = 0; kh2 < 2; kh2++) {
            uint32_t vh[8][2], vl[8][2];
#pragma unroll
            for (int dh = 0; dh < 4; dh++) {
                uint32_t ro = (uint32_t)(dh * 16 + lrow) * 128 +
                              (uint32_t)(wn * 32 + kh2 * 16) * 2 + lkh * 16;
                uint32_t r0, r1, r2, r3;
                ldsm_x4(r0, r1, r2, r3, vbh + SWZ(ro));
                vh[dh * 2 + 0][0] = r0; vh[dh * 2 + 0][1] = r2;
                vh[dh * 2 + 1][0] = r1; vh[dh * 2 + 1][1] = r3;
                ldsm_x4(r0, r1, r2, r3, vbl + SWZ(ro));
                vl[dh * 2 + 0][0] = r0; vl[dh * 2 + 0][1] = r2;
                vl[dh * 2 + 1][0] = r1; vl[dh * 2 + 1][1] = r3;
            }
#pragma unroll
            for (int ms = 0; ms < 2; ms++) {
                const float* c0 = acc[ms][2 * kh2];
                const float* c1 = acc[ms][2 * kh2 + 1];
                uint32_t ph[4];
                ph[0] = pack_half(c0[0], c0[1]);
                ph[1] = pack_half(c0[2], c0[3]);
                ph[2] = pack_half(c1[0], c1[1]);
                ph[3] = pack_half(c1[2], c1[3]);
#pragma unroll
                for (int dn = 0; dn < 8; dn++) {
                    mma_f16(accO[ms][dn], ph, vh[dn][0], vh[dn][1]);
                    mma_f16(accO[ms][dn], ph, vl[dn][0], vl[dn][1]);
                }
            }
        }
        __syncthreads();
    }

    // ---- ctx epilogue: cross-wn reduce in smem, bf16 split store [B,S,D] ----
    float* st = (float*)dsm;
    {
        const int lc2 = lc * 2;
        if (wn == 0) {
#pragma unroll
            for (int ms = 0; ms < 2; ms++)
#pragma unroll
                for (int dn = 0; dn < 8; dn++) {
                    int r = wm * 32 + ms * 16 + lr;
                    int c = dn * 8 + lc2;
                    st[r * 65 + c]           = accO[ms][dn][0];
                    st[r * 65 + c + 1]       = accO[ms][dn][1];
                    st[(r + 8) * 65 + c]     = accO[ms][dn][2];
                    st[(r + 8) * 65 + c + 1] = accO[ms][dn][3];
                }
        }
        __syncthreads();
        if (wn == 1) {
#pragma unroll
            for (int ms = 0; ms < 2; ms++)
#pragma unroll
                for (int dn = 0; dn < 8; dn++) {
                    int r = wm * 32 + ms * 16 + lr;
                    int c = dn * 8 + lc2;
                    st[r * 65 + c]           += accO[ms][dn][0];
                    st[r * 65 + c + 1]       += accO[ms][dn][1];
                    st[(r + 8) * 65 + c]     += accO[ms][dn][2];
                    st[(r + 8) * 65 + c + 1] += accO[ms][dn][3];
                }
        }
        __syncthreads();
    }
    {
        const int b = z >> 4, hh = z & 15;
        for (int i = tid; i < 128 * 64; i += 256) {
            int row = i >> 6, c = i & 63;
            float v = st[row * 65 + c];
            long o = (long)((b << 11) + m0 + row) * 1024 + hh * 64 + c;
            __nv_bfloat16 h = __float2bfloat16(v);
            ch[o] = h;
            cl[o] = __float2bfloat16(v - __bfloat162float(h));
        }
    }
}

// ---------------------------------------------------------------------------
extern "C" void kernel_launch(void* const* d_in, const int* in_sizes, int n_in,
                              void* d_out, int out_size)
{
    const float* Q  = (const float*)d_in[0];
    const float* K  = (const float*)d_in[1];
    const float* V  = (const float*)d_in[2];
    const float* Wq = (const float*)d_in[3];
    const float* bq = (const float*)d_in[4];
    const float* Wk = (const float*)d_in[5];
    const float* bk = (const float*)d_in[6];
    const float* Wv = (const float*)d_in[7];
    const float* bv = (const float*)d_in[8];
    const float* Wo = (const float*)d_in[9];
    const float* bo = (const float*)d_in[10];
    float* out = (float*)d_out;

    __nv_bfloat16 *Qh, *Ql, *Kh, *Kl, *Vh, *Vl;
    __nv_bfloat16 *Wqh, *Wql, *Wkh, *Wkl, *Wvh, *Wvl, *Woh, *Wol;
    __half *qh, *kh, *vth, *vtl;
    __nv_bfloat16 *ch, *cl;
    float* attn_scratch;
    cudaGetSymbolAddress((void**)&Qh, g_Qh);   cudaGetSymbolAddress((void**)&Ql, g_Ql);
    cudaGetSymbolAddress((void**)&Kh, g_Kh);   cudaGetSymbolAddress((void**)&Kl, g_Kl);
    cudaGetSymbolAddress((void**)&Vh, g_Vh);   cudaGetSymbolAddress((void**)&Vl, g_Vl);
    cudaGetSymbolAddress((void**)&Wqh, g_Wqh); cudaGetSymbolAddress((void**)&Wql, g_Wql);
    cudaGetSymbolAddress((void**)&Wkh, g_Wkh); cudaGetSymbolAddress((void**)&Wkl, g_Wkl);
    cudaGetSymbolAddress((void**)&Wvh, g_Wvh); cudaGetSymbolAddress((void**)&Wvl, g_Wvl);
    cudaGetSymbolAddress((void**)&Woh, g_Woh); cudaGetSymbolAddress((void**)&Wol, g_Wol);
    cudaGetSymbolAddress((void**)&qh, g_qh);
    cudaGetSymbolAddress((void**)&kh, g_kh);
    cudaGetSymbolAddress((void**)&vth, g_vth); cudaGetSymbolAddress((void**)&vtl, g_vtl);
    cudaGetSymbolAddress((void**)&ch, g_ch);   cudaGetSymbolAddress((void**)&cl, g_cl);
    cudaGetSymbolAddress((void**)&attn_scratch, g_attn);

    float* attn = ((long)out_size >= OUT_TOTAL) ? (out + OUT0) : attn_scratch;

    cudaFuncSetAttribute(mma_proj3,   cudaFuncAttributeMaxDynamicSharedMemorySize, SM_PIPE);
    cudaFuncSetAttribute(mma_outproj, cudaFuncAttributeMaxDynamicSharedMemorySize, SM_PIPE);
    cudaFuncSetAttribute(fused_attn_k, cudaFuncAttributeMaxDynamicSharedMemorySize, FB_SM);

    // 0) One-launch split of all 7 fp32 inputs into bf16 hi/lo
    {
        SplitArgs a;
        a.x[0] = Q;  a.h[0] = Qh;  a.l[0] = Ql;  a.n4[0] = TOKENS * DMODEL / 4;
        a.x[1] = K;  a.h[1] = Kh;  a.l[1] = Kl;  a.n4[1] = TOKENS * DMODEL / 4;
        a.x[2] = V;  a.h[2] = Vh;  a.l[2] = Vl;  a.n4[2] = TOKENS * DMODEL / 4;
        a.x[3] = Wq; a.h[3] = Wqh; a.l[3] = Wql; a.n4[3] = DMODEL * DMODEL / 4;
        a.x[4] = Wk; a.h[4] = Wkh; a.l[4] = Wkl; a.n4[4] = DMODEL * DMODEL / 4;
        a.x[5] = Wv; a.h[5] = Wvh; a.l[5] = Wvl; a.n4[5] = DMODEL * DMODEL / 4;
        a.x[6] = Wo; a.h[6] = Woh; a.l[6] = Wol; a.n4[6] = DMODEL * DMODEL / 4;
        dim3 gs((TOKENS * DMODEL / 4 + 255) / 256, 7, 1);
        split_all<<<gs, 256>>>(a);
    }

    // 1) Merged Q/K/V projections in ONE launch (grid.z = 3)
    {
        ProjArgs pa;
        pa.Ah[0] = Qh; pa.Al[0] = Ql; pa.Bh[0] = Wqh; pa.Bl[0] = Wql;
        pa.bias[0] = bq; pa.outH[0] = qh; pa.outL[0] = nullptr;
        pa.Ah[1] = Kh; pa.Al[1] = Kl; pa.Bh[1] = Wkh; pa.Bl[1] = Wkl;
        pa.bias[1] = bk; pa.outH[1] = kh; pa.outL[1] = nullptr;
        pa.Ah[2] = Vh; pa.Al[2] = Vl; pa.Bh[2] = Wvh; pa.Bl[2] = Wvl;
        pa.bias[2] = bv; pa.outH[2] = vth; pa.outL[2] = vtl;
        dim3 gp(DMODEL / NT, TOKENS / MT, 3);                   // (16, 32, 3)
        mma_proj3<<<gp, 256, SM_PIPE>>>(pa);
    }

    // 2) Fused scores + softmax + context (1-pass S, 2-pass O)
    dim3 gf(SEQ / 128, BH, 1);                                  // (16, 32)
    fused_attn_k<<<gf, 256, FB_SM>>>(qh, kh, vth, vtl, attn, ch, cl);

    // 3) Output projection: ctx @ Wo^T + bo -> out fp32
    dim3 go(DMODEL / NT, TOKENS / MT, 1);
    mma_outproj<<<go, 256, SM_PIPE>>>(ch, cl, Woh, Wol, bo, out);

    (void)n_in; (void)in_sizes;
}